// round 11
// baseline (speedup 1.0000x reference)
#include <cuda_runtime.h>
#include <cuda_bf16.h>
#include <math.h>
#include <stdint.h>

#define T_TOK 64
#define S_SP  729
#define H_DIM 1152
#define E_DIM 512
#define NE    9
#define NL    4
#define B_IMG 8
#define P_PAT 8

#define OUT_MAJOR 0
#define OUT_FINAL (T_TOK * 4 * H_DIM)
#define OUT_PREDS (OUT_FINAL + B_IMG * H_DIM)

__device__ float g_poolpart[B_IMG * 9 * H_DIM];
__device__ float g_prompts[NL * B_IMG * NE * E_DIM];
__device__ float g_part   [(size_t)NL * T_TOK * 2 * 10 * S_SP];   // 14.9 MB
__device__ float g_meanatt[T_TOK * NE * S_SP];
__device__ float g_pes    [T_TOK * NE];
__device__ float g_gsig   [T_TOK * 4];
__device__ __align__(16) __nv_bfloat16 g_Whi[(size_t)NL * E_DIM * H_DIM];
__device__ __align__(16) __nv_bfloat16 g_Wlo[(size_t)NL * E_DIM * H_DIM];

__device__ __forceinline__ uint32_t smem_u32(const void* p) {
    uint32_t a;
    asm("{ .reg .u64 t; cvta.to.shared.u64 t, %1; cvt.u32.u64 %0, t; }" : "=r"(a) : "l"(p));
    return a;
}
__device__ __forceinline__ void cpasync16(uint32_t dst, const void* src) {
    asm volatile("cp.async.cg.shared.global [%0], [%1], 16;" :: "r"(dst), "l"(src));
}
#define CP_COMMIT() asm volatile("cp.async.commit_group;" ::: "memory")
#define CP_WAIT1()  asm volatile("cp.async.wait_group 1;" ::: "memory")

__device__ __forceinline__ float blockSum256(float v) {
    __shared__ float red[8];
    int lane = threadIdx.x & 31, wid = threadIdx.x >> 5;
    #pragma unroll
    for (int o = 16; o; o >>= 1) v += __shfl_xor_sync(0xffffffffu, v, o);
    if (lane == 0) red[wid] = v;
    __syncthreads();
    if (wid == 0) {
        float r = (lane < 8) ? red[lane] : 0.f;
        #pragma unroll
        for (int o = 4; o; o >>= 1) r += __shfl_xor_sync(0xffffffffu, r, o);
        if (lane == 0) red[0] = r;
    }
    __syncthreads();
    float r = red[0];
    __syncthreads();
    return r;
}
__device__ __forceinline__ float blockMax256(float v) {
    __shared__ float red[8];
    int lane = threadIdx.x & 31, wid = threadIdx.x >> 5;
    #pragma unroll
    for (int o = 16; o; o >>= 1) v = fmaxf(v, __shfl_xor_sync(0xffffffffu, v, o));
    if (lane == 0) red[wid] = v;
    __syncthreads();
    if (wid == 0) {
        float r = (lane < 8) ? red[lane] : -INFINITY;
        #pragma unroll
        for (int o = 4; o; o >>= 1) r = fmaxf(r, __shfl_xor_sync(0xffffffffu, r, o));
        if (lane == 0) red[0] = r;
    }
    __syncthreads();
    float r = red[0];
    __syncthreads();
    return r;
}
__device__ __forceinline__ float gelu_exact(float x) {
    return 0.5f * x * (1.0f + erff(x * 0.7071067811865475f));
}
__device__ __forceinline__ uint32_t pk2(__nv_bfloat16 a, __nv_bfloat16 b) {
    return ((uint32_t)__bfloat16_as_ushort(b) << 16) | (uint32_t)__bfloat16_as_ushort(a);
}
__device__ __forceinline__ void mma16816(float* d, const uint32_t* a, uint32_t b0, uint32_t b1) {
    asm volatile(
        "mma.sync.aligned.m16n8k16.row.col.f32.bf16.bf16.f32 "
        "{%0,%1,%2,%3}, {%4,%5,%6,%7}, {%8,%9}, {%0,%1,%2,%3};"
        : "+f"(d[0]), "+f"(d[1]), "+f"(d[2]), "+f"(d[3])
        : "r"(a[0]), "r"(a[1]), "r"(a[2]), "r"(a[3]), "r"(b0), "r"(b1));
}

// launch 0
__global__ void k_wsplit(const float* __restrict__ sw) {
    const size_t N = (size_t)NL * E_DIM * H_DIM;
    for (size_t i = (size_t)blockIdx.x * 256 + threadIdx.x; i < N; i += (size_t)gridDim.x * 256) {
        float w = sw[i];
        __nv_bfloat16 h = __float2bfloat16(w);
        g_Whi[i] = h;
        g_Wlo[i] = __float2bfloat16(w - __bfloat162float(h));
    }
}

// launch 1: pooled partials, grid (8,9), block 128
__global__ void k_pool(const float* __restrict__ ov, const float* __restrict__ pw) {
    int b = blockIdx.x, sc = blockIdx.y, tid = threadIdx.x;
    float acc[9];
    #pragma unroll
    for (int j = 0; j < 9; j++) acc[j] = 0.f;
    const float* base = ov + (size_t)(b * P_PAT) * S_SP * H_DIM + (size_t)sc * 81 * H_DIM + tid;
    for (int s = 0; s < 81; s++) {
        float w = pw[sc * 81 + s];
        const float* p = base + (size_t)s * H_DIM;
        #pragma unroll
        for (int j = 0; j < 9; j++) acc[j] += w * p[j * 128];
    }
    #pragma unroll
    for (int j = 0; j < 9; j++)
        g_poolpart[((size_t)b * 9 + sc) * H_DIM + tid + j * 128] = acc[j];
}

// launch 2: fused cls chain + prompt adaptor, grid (8, 4) = (b, i), block 256
__global__ void __launch_bounds__(256, 1)
k_pre(const float* __restrict__ w1, const float* __restrict__ b1,
      const float* __restrict__ pb,
      const float* __restrict__ w2, const float* __restrict__ b2,
      const float* __restrict__ emo, const float* __restrict__ pw,
      const float* __restrict__ prm_b) {
    __shared__ float pooled[H_DIM];
    __shared__ float hidden[E_DIM];
    __shared__ float clsS[E_DIM];
    __shared__ float es[NE * E_DIM];
    __shared__ float rawP[NE * E_DIM];
    int b = blockIdx.x, i = blockIdx.y;
    int tid = threadIdx.x, wid = tid >> 5, lane = tid & 31;

    float pbias = pb[0];
    for (int h = tid; h < H_DIM; h += 256) {
        float s = pbias;
        #pragma unroll
        for (int sc = 0; sc < 9; sc++) s += g_poolpart[((size_t)b * 9 + sc) * H_DIM + h];
        pooled[h] = s;
    }
    for (int idx = tid; idx < NE * E_DIM; idx += 256) es[idx] = emo[idx];
    __syncthreads();

    // hidden = gelu(pooled @ w1^T + b1)
    for (int o = wid; o < E_DIM; o += 8) {
        float acc = 0.f;
        const float* wr = w1 + (size_t)o * H_DIM;
        for (int k = lane; k < H_DIM; k += 32) acc += wr[k] * pooled[k];
        #pragma unroll
        for (int off = 16; off; off >>= 1) acc += __shfl_xor_sync(0xffffffffu, acc, off);
        if (lane == 0) hidden[o] = gelu_exact(acc + b1[o]);
    }
    __syncthreads();

    // cls = hidden @ w2^T + b2
    for (int o = wid; o < E_DIM; o += 8) {
        float acc = 0.f;
        const float* wr = w2 + (size_t)o * E_DIM;
        for (int k = lane; k < E_DIM; k += 32) acc += wr[k] * hidden[k];
        #pragma unroll
        for (int off = 16; off; off >>= 1) acc += __shfl_xor_sync(0xffffffffu, acc, off);
        if (lane == 0) clsS[o] = acc + b2[o];
    }
    __syncthreads();

    // raw[n][o] = pw[i,o,0:512].emo[n] + pw[i,o,512:1024].cls + prm_b[i,o]
    for (int o = wid; o < E_DIM; o += 8) {
        const float* wr = pw + ((size_t)i * E_DIM + o) * 1024;
        float acc[10];
        #pragma unroll
        for (int j = 0; j < 10; j++) acc[j] = 0.f;
        for (int c = lane; c < 512; c += 32) {
            float wa = wr[c];
            #pragma unroll
            for (int n = 0; n < NE; n++) acc[n] += wa * es[n * 512 + c];
            acc[9] += wr[512 + c] * clsS[c];
        }
        #pragma unroll
        for (int j = 0; j < 10; j++)
            #pragma unroll
            for (int off = 16; off; off >>= 1) acc[j] += __shfl_xor_sync(0xffffffffu, acc[j], off);
        if (lane == 0) {
            float bias = prm_b[i * 512 + o];
            #pragma unroll
            for (int n = 0; n < NE; n++) rawP[n * 512 + o] = acc[n] + acc[9] + bias;
        }
    }
    __syncthreads();

    // normalize per n, write g_prompts
    for (int n = wid; n < NE; n += 8) {
        float vals[16];
        float nsq = 0.f;
        #pragma unroll
        for (int j = 0; j < 16; j++) {
            float x = rawP[n * 512 + lane + j * 32];
            vals[j] = x;
            nsq += x * x;
        }
        #pragma unroll
        for (int off = 16; off; off >>= 1) nsq += __shfl_xor_sync(0xffffffffu, nsq, off);
        float inv = rsqrtf(nsq);
        size_t base = ((size_t)(i * B_IMG + b) * NE + n) * E_DIM;
        #pragma unroll
        for (int j = 0; j < 16; j++) g_prompts[base + lane + j * 32] = vals[j] * inv;
    }
}

// ======= launch 3 (ncu slot): sig GEMM, N halved, 2 CTAs/SM, grid (12,64,8) =======
#define NCH 36
#define SM2_PSM   0
#define SM2_SBI   9216
#define SM2_RED   10240
#define SM2_A     12800
#define SM2_W     33280
#define SM2_YSM   12800
#define SM2_TOTAL 115200
#define Y_STR 260

__global__ void __launch_bounds__(256, 2)
k_sig_mma(const float* __restrict__ sig, const float* __restrict__ sb) {
    extern __shared__ char smem[];
    uint32_t sbase = smem_u32(smem);
    float* Psm = reinterpret_cast<float*>(smem + SM2_PSM);
    float* Sbi = reinterpret_cast<float*>(smem + SM2_SBI);
    float* red = reinterpret_cast<float*>(smem + SM2_RED);
    float* ysm = reinterpret_cast<float*>(smem + SM2_YSM);

    int tid = threadIdx.x, wid = tid >> 5, lane = tid & 31;
    int wm = wid >> 2, wn = wid & 3;
    int g = lane >> 2, tig = lane & 3;
    int s0 = blockIdx.x * 64;
    int t = blockIdx.y;
    int i = blockIdx.z >> 1, half = blockIdx.z & 1;
    int b = t >> 3;

    {
        size_t pbase = ((size_t)(i * B_IMG + b) * NE) * E_DIM + half * 256;
        for (int idx = tid; idx < NE * 256; idx += 256) {
            int n = idx >> 8, cc = idx & 255;
            Psm[idx] = g_prompts[pbase + (size_t)n * E_DIM + cc];
        }
        for (int idx = tid; idx < 256; idx += 256) Sbi[idx] = sb[i * E_DIM + half * 256 + idx];
        for (int idx = tid; idx < 640; idx += 256) red[idx] = 0.f;
    }

    const float* Xbase = sig + ((size_t)(i * T_TOK + t) * S_SP) * H_DIM;
    const char* WH = reinterpret_cast<const char*>(g_Whi)
                   + ((size_t)i * E_DIM + half * 256) * H_DIM * 2;
    const char* WL = reinterpret_cast<const char*>(g_Wlo)
                   + ((size_t)i * E_DIM + half * 256) * H_DIM * 2;

    float acc[2][8][4];
    #pragma unroll
    for (int mt = 0; mt < 2; mt++)
        #pragma unroll
        for (int nt = 0; nt < 8; nt++)
            #pragma unroll
            for (int c = 0; c < 4; c++) acc[mt][nt][c] = 0.f;

    int xrow = tid >> 2, xkc = tid & 3;
    int xs = s0 + xrow;
    const float* xptr = (xs < S_SP) ? (Xbase + (size_t)xs * H_DIM + xkc * 8) : nullptr;
    float xv[8];

#define ISSUE_W(CH, BUF) do { \
    uint32_t wHi = sbase + SM2_W + (BUF) * 40960; \
    int n_ = tid; \
    const char* sH = WH + ((size_t)n_ * H_DIM + (CH) * 32) * 2; \
    const char* sL = WL + ((size_t)n_ * H_DIM + (CH) * 32) * 2; \
    uint32_t dH = wHi + n_ * 80; \
    uint32_t dL = dH + 20480; \
    cpasync16(dH, sH); cpasync16(dH + 16, sH + 16); \
    cpasync16(dH + 32, sH + 32); cpasync16(dH + 48, sH + 48); \
    cpasync16(dL, sL); cpasync16(dL + 16, sL + 16); \
    cpasync16(dL + 32, sL + 32); cpasync16(dL + 48, sL + 48); \
} while (0)

#define LOAD_X(CH) do { \
    if (xptr) { \
        const float* p_ = xptr + (CH) * 32; \
        float4 f0_ = *reinterpret_cast<const float4*>(p_); \
        float4 f1_ = *reinterpret_cast<const float4*>(p_ + 4); \
        xv[0]=f0_.x; xv[1]=f0_.y; xv[2]=f0_.z; xv[3]=f0_.w; \
        xv[4]=f1_.x; xv[5]=f1_.y; xv[6]=f1_.z; xv[7]=f1_.w; \
    } else { \
        _Pragma("unroll") for (int j_ = 0; j_ < 8; j_++) xv[j_] = 0.f; \
    } \
} while (0)

#define STORE_A(BUF) do { \
    uint32_t hq_[4], lq_[4]; \
    _Pragma("unroll") \
    for (int j_ = 0; j_ < 4; j_++) { \
        __nv_bfloat16 h0_ = __float2bfloat16(xv[2*j_]); \
        __nv_bfloat16 h1_ = __float2bfloat16(xv[2*j_+1]); \
        __nv_bfloat16 l0_ = __float2bfloat16(xv[2*j_]   - __bfloat162float(h0_)); \
        __nv_bfloat16 l1_ = __float2bfloat16(xv[2*j_+1] - __bfloat162float(h1_)); \
        hq_[j_] = pk2(h0_, h1_); \
        lq_[j_] = pk2(l0_, l1_); \
    } \
    char* aH = smem + SM2_A + (BUF) * 10240 + xrow * 80 + xkc * 16; \
    *reinterpret_cast<uint4*>(aH)        = make_uint4(hq_[0], hq_[1], hq_[2], hq_[3]); \
    *reinterpret_cast<uint4*>(aH + 5120) = make_uint4(lq_[0], lq_[1], lq_[2], lq_[3]); \
} while (0)

    ISSUE_W(0, 0); CP_COMMIT();
    LOAD_X(0);
    ISSUE_W(1, 1); CP_COMMIT();
    STORE_A(0);
    LOAD_X(1);

    for (int ch = 0; ch < NCH; ch++) {
        int buf = ch & 1;
        if (ch > 0) {
            STORE_A(buf);
            if (ch + 1 < NCH) LOAD_X(ch + 1);
        }
        CP_WAIT1();
        __syncthreads();

        const uint32_t* AH  = reinterpret_cast<const uint32_t*>(smem + SM2_A + buf * 10240);
        const uint32_t* AL  = AH + 1280;
        const uint32_t* WHs = reinterpret_cast<const uint32_t*>(smem + SM2_W + buf * 40960);
        const uint32_t* WLs = WHs + 5120;

        #pragma unroll
        for (int h = 0; h < 2; h++) {
            uint32_t ah[2][4], al[2][4];
            #pragma unroll
            for (int mt = 0; mt < 2; mt++) {
                int base = (wm * 32 + mt * 16 + g) * 20 + h * 8 + tig;
                ah[mt][0] = AH[base];     ah[mt][1] = AH[base + 160];
                ah[mt][2] = AH[base + 4]; ah[mt][3] = AH[base + 164];
                al[mt][0] = AL[base];     al[mt][1] = AL[base + 160];
                al[mt][2] = AL[base + 4]; al[mt][3] = AL[base + 164];
            }
            #pragma unroll
            for (int nt = 0; nt < 8; nt++) {
                int wb = (wn * 64 + nt * 8 + g) * 20 + h * 8 + tig;
                uint32_t b0h = WHs[wb], b1h = WHs[wb + 4];
                uint32_t b0l = WLs[wb], b1l = WLs[wb + 4];
                #pragma unroll
                for (int mt = 0; mt < 2; mt++) {
                    mma16816(acc[mt][nt], ah[mt], b0h, b1h);
                    mma16816(acc[mt][nt], ah[mt], b0l, b1l);
                    mma16816(acc[mt][nt], al[mt], b0h, b1h);
                }
            }
        }
        __syncthreads();
        if (ch + 2 < NCH) ISSUE_W(ch + 2, buf);
        CP_COMMIT();
    }

    // epilogue: bias + partial L2-norm + partial 9 prompt dots for this half
    #pragma unroll
    for (int mt = 0; mt < 2; mt++) {
        int row = wm * 32 + mt * 16 + g;
        #pragma unroll
        for (int nt = 0; nt < 8; nt++) {
            int col = wn * 64 + nt * 8 + tig * 2;
            float b0 = Sbi[col], b1 = Sbi[col + 1];
            *reinterpret_cast<float2*>(&ysm[row * Y_STR + col]) =
                make_float2(acc[mt][nt][0] + b0, acc[mt][nt][1] + b1);
            *reinterpret_cast<float2*>(&ysm[(row + 8) * Y_STR + col]) =
                make_float2(acc[mt][nt][2] + b0, acc[mt][nt][3] + b1);
        }
    }
    __syncthreads();
    for (int r8 = 0; r8 < 8; r8++) {
        int row = wid * 8 + r8;
        float v[10];
        #pragma unroll
        for (int j = 0; j < 10; j++) v[j] = 0.f;
        for (int cc = lane; cc < 256; cc += 32) {
            float y = ysm[row * Y_STR + cc];
            v[0] += y * y;
            #pragma unroll
            for (int n = 0; n < NE; n++) v[1 + n] += y * Psm[n * 256 + cc];
        }
        #pragma unroll
        for (int j = 0; j < 10; j++)
            #pragma unroll
            for (int off = 16; off; off >>= 1) v[j] += __shfl_xor_sync(0xffffffffu, v[j], off);
        if (lane == 0) {
            #pragma unroll
            for (int j = 0; j < 10; j++) red[row * 10 + j] = v[j];
        }
    }
    __syncthreads();

    if (tid < 64) {
        int s = s0 + tid;
        if (s < S_SP) {
            size_t base = ((((size_t)i * T_TOK + t) * 2 + half) * 10) * S_SP + s;
            #pragma unroll
            for (int j = 0; j < 10; j++)
                g_part[base + (size_t)j * S_SP] = red[tid * 10 + j];
        }
    }
#undef ISSUE_W
#undef LOAD_X
#undef STORE_A
}

// launch 4: combine partials + softmax + level mean
__global__ void k_softmax_mean() {
    int tn = blockIdx.x;
    int t = tn / NE, n = tn % NE;
    int tid = threadIdx.x;
    float accm[3] = {0.f, 0.f, 0.f};
    for (int i = 0; i < NL; i++) {
        const float* p0 = g_part + ((((size_t)i * T_TOK + t) * 2 + 0) * 10) * S_SP;
        const float* p1 = g_part + ((((size_t)i * T_TOK + t) * 2 + 1) * 10) * S_SP;
        float x[3];
        float mx = -INFINITY;
        #pragma unroll
        for (int j = 0; j < 3; j++) {
            int s = tid + j * 256;
            if (s < S_SP) {
                float nsq = p0[s] + p1[s];
                float d = p0[(size_t)(1 + n) * S_SP + s] + p1[(size_t)(1 + n) * S_SP + s];
                x[j] = 100.f * d * rsqrtf(nsq);
            } else x[j] = -INFINITY;
            mx = fmaxf(mx, x[j]);
        }
        mx = blockMax256(mx);
        float lsum = 0.f;
        float e[3];
        #pragma unroll
        for (int j = 0; j < 3; j++) {
            int s = tid + j * 256;
            e[j] = (s < S_SP) ? expf(x[j] - mx) : 0.f;
            lsum += e[j];
        }
        float tot = blockSum256(lsum);
        float inv = 0.25f / tot;
        #pragma unroll
        for (int j = 0; j < 3; j++) accm[j] += e[j] * inv;
    }
    float psum = 0.f;
    size_t obase = ((size_t)t * NE + n) * S_SP;
    #pragma unroll
    for (int j = 0; j < 3; j++) {
        int s = tid + j * 256;
        if (s < S_SP) {
            g_meanatt[obase + s] = accm[j];
            psum += accm[j];
        }
    }
    float tot = blockSum256(psum);
    if (tid == 0) g_pes[t * NE + n] = tot / (float)S_SP;
}

// launch 5: fused tail; quadrant weights precomputed (no div in hot loops)
__global__ void k_tail(const float* __restrict__ ov,
                       const float* __restrict__ qw, const float* __restrict__ qb,
                       const float* __restrict__ kw, const float* __restrict__ kb,
                       float* __restrict__ out) {
    extern __shared__ float S[];
    float* matt = S;               // 736
    float* sp   = S + 736;         // 4
    float* qkb  = S + 740;         // 4
    float* pmx  = S + 744;         // 8 pad
    float* wq   = S + 752;         // 4*736 = 2944
    float* toks = S + 3696;        // 4608
    float* Qs   = toks + 4608;     // 2048
    float* KQs  = Qs + 2048;       // 4608
    float* law  = KQs + 4608;      // 2916

    int t = blockIdx.x, tid = threadIdx.x;
    int wid = tid >> 5, lane = tid & 31;

    float bsum[4] = {0.f, 0.f, 0.f, 0.f};
    for (int s = tid; s < S_SP; s += 256) {
        float m = -INFINITY;
        #pragma unroll
        for (int n = 0; n < NE; n++)
            m = fmaxf(m, g_meanatt[((size_t)t * NE + n) * S_SP + s]);
        matt[s] = m;
        int r = s / 27, c = s - r * 27;
        float w0 = (r < 14 && c < 14) ? m : 0.f;
        float w1 = (r < 14 && c >= 13) ? m : 0.f;
        float w2 = (r >= 13 && c < 14) ? m : 0.f;
        float w3 = (r >= 13 && c >= 13) ? m : 0.f;
        wq[0 * 736 + s] = w0;
        wq[1 * 736 + s] = w1;
        wq[2 * 736 + s] = w2;
        wq[3 * 736 + s] = w3;
        bsum[0] += w0; bsum[1] += w1; bsum[2] += w2; bsum[3] += w3;
    }
    #pragma unroll
    for (int q = 0; q < 4; q++) {
        float tot = blockSum256(bsum[q]);
        if (tid == 0) sp[q] = tot / 196.f;
    }
    if (tid == 0) {
        float pm = -INFINITY;
        for (int n = 0; n < NE; n++) pm = fmaxf(pm, g_pes[t * NE + n]);
        pmx[0] = pm;
    }
    __syncthreads();
    if (tid < 4) g_gsig[t * 4 + tid] = sp[tid] * pmx[0];

    // tokens (div-free inner loop)
    {
        int nh = (tid < 128) ? 5 : 4;
        float accT[5][4];
        #pragma unroll
        for (int j = 0; j < 5; j++)
            #pragma unroll
            for (int q = 0; q < 4; q++) accT[j][q] = 0.f;
        const float* obase = ov + ((size_t)t * S_SP) * H_DIM + tid;
        for (int s = 0; s < S_SP; s++) {
            float w0 = wq[s], w1 = wq[736 + s], w2 = wq[1472 + s], w3 = wq[2208 + s];
            const float* p = obase + (size_t)s * H_DIM;
            #pragma unroll
            for (int j = 0; j < 5; j++) {
                if (j < nh) {
                    float v = p[j * 256];
                    accT[j][0] += v * w0;
                    accT[j][1] += v * w1;
                    accT[j][2] += v * w2;
                    accT[j][3] += v * w3;
                }
            }
        }
        for (int j = 0; j < nh; j++) {
            int h = tid + j * 256;
            #pragma unroll
            for (int q = 0; q < 4; q++)
                toks[q * H_DIM + h] = (accT[j][q] * (1.f / 196.f)) / (sp[q] + 1e-8f);
        }
    }
    __syncthreads();

    for (int o = wid; o < E_DIM; o += 8) {
        float acc[4] = {0.f, 0.f, 0.f, 0.f};
        const float* wr = qw + (size_t)o * H_DIM;
        for (int k = lane; k < H_DIM; k += 32) {
            float w = wr[k];
            #pragma unroll
            for (int q = 0; q < 4; q++) acc[q] += w * toks[q * H_DIM + k];
        }
        #pragma unroll
        for (int off = 16; off; off >>= 1)
            #pragma unroll
            for (int q = 0; q < 4; q++) acc[q] += __shfl_xor_sync(0xffffffffu, acc[q], off);
        if (lane == 0) {
            float bv = qb[o];
            #pragma unroll
            for (int q = 0; q < 4; q++) Qs[q * E_DIM + o] = acc[q] + bv;
        }
    }
    __syncthreads();
    if (wid < 4) {
        float acc = 0.f;
        for (int e = lane; e < E_DIM; e += 32) acc += Qs[wid * E_DIM + e] * kb[e];
        #pragma unroll
        for (int off = 16; off; off >>= 1) acc += __shfl_xor_sync(0xffffffffu, acc, off);
        if (lane == 0) qkb[wid] = acc;
    }
    __syncthreads();

    {
        float a[5][4];
        #pragma unroll
        for (int j = 0; j < 5; j++)
            #pragma unroll
            for (int q = 0; q < 4; q++) a[j][q] = 0.f;
        for (int e = 0; e < E_DIM; e++) {
            float q0 = Qs[e], q1 = Qs[512 + e], q2 = Qs[1024 + e], q3 = Qs[1536 + e];
            const float* kr = kw + (size_t)e * H_DIM;
            #pragma unroll
            for (int j = 0; j < 5; j++) {
                int h = j * 256 + tid;
                if (h < H_DIM) {
                    float kv = kr[h];
                    a[j][0] += kv * q0; a[j][1] += kv * q1;
                    a[j][2] += kv * q2; a[j][3] += kv * q3;
                }
            }
        }
        #pragma unroll
        for (int j = 0; j < 5; j++) {
            int h = j * 256 + tid;
            if (h < H_DIM) {
                #pragma unroll
                for (int q = 0; q < 4; q++) KQs[q * H_DIM + h] = a[j][q];
            }
        }
    }
    __syncthreads();

    const float RS = 0.04419417382415922f;
    for (int s = wid; s < S_SP; s += 8) {
        float acc[4] = {0.f, 0.f, 0.f, 0.f};
        const float* orow = ov + ((size_t)t * S_SP + s) * H_DIM;
        for (int h = lane; h < H_DIM; h += 32) {
            float vv = orow[h];
            #pragma unroll
            for (int q = 0; q < 4; q++) acc[q] += vv * KQs[q * H_DIM + h];
        }
        #pragma unroll
        for (int off = 16; off; off >>= 1)
            #pragma unroll
            for (int q = 0; q < 4; q++) acc[q] += __shfl_xor_sync(0xffffffffu, acc[q], off);
        if (lane == 0) {
            #pragma unroll
            for (int q = 0; q < 4; q++) law[q * S_SP + s] = (acc[q] + qkb[q]) * RS;
        }
    }
    __syncthreads();
    for (int q = 0; q < 4; q++) {
        float mx = -INFINITY;
        for (int s = tid; s < S_SP; s += 256) mx = fmaxf(mx, law[q * S_SP + s]);
        mx = blockMax256(mx);
        float lsum = 0.f;
        for (int s = tid; s < S_SP; s += 256) {
            float e = expf(law[q * S_SP + s] - mx);
            law[q * S_SP + s] = e;
            lsum += e;
        }
        float tot = blockSum256(lsum);
        float inv = 1.f / tot;
        for (int s = tid; s < S_SP; s += 256) law[q * S_SP + s] *= inv;
        __syncthreads();
    }

    {
        int nh = (tid < 128) ? 5 : 4;
        float macc[5][4];
        #pragma unroll
        for (int j = 0; j < 5; j++)
            #pragma unroll
            for (int q = 0; q < 4; q++) macc[j][q] = 0.f;
        const float* obase = ov + ((size_t)t * S_SP) * H_DIM + tid;
        for (int s = 0; s < S_SP; s++) {
            float a0 = law[0 * S_SP + s], a1 = law[1 * S_SP + s];
            float a2 = law[2 * S_SP + s], a3 = law[3 * S_SP + s];
            const float* p = obase + (size_t)s * H_DIM;
            #pragma unroll
            for (int j = 0; j < 5; j++) {
                if (j < nh) {
                    float v = p[j * 256];
                    macc[j][0] += a0 * v;
                    macc[j][1] += a1 * v;
                    macc[j][2] += a2 * v;
                    macc[j][3] += a3 * v;
                }
            }
        }
        for (int j = 0; j < nh; j++) {
            int h = tid + j * 256;
            #pragma unroll
            for (int q = 0; q < 4; q++)
                out[OUT_MAJOR + ((size_t)t * 4 + q) * H_DIM + h] = macc[j][q];
        }
    }
}

// launch 6: fused final + preds
__global__ void k_finpred(const float* __restrict__ w1, const float* __restrict__ b1,
                          const float* __restrict__ w2, const float* __restrict__ b2,
                          float* __restrict__ out) {
    int b = blockIdx.x, tid = threadIdx.x;
    __shared__ float gsh[32];
    __shared__ float gsum_sh;
    __shared__ float fr[H_DIM];
    __shared__ float hid[E_DIM];
    __shared__ float lg[NE];
    if (tid < 32) {
        int p = tid >> 2, q = tid & 3;
        gsh[tid] = g_gsig[(b * P_PAT + p) * 4 + q];
    }
    __syncthreads();
    if (tid == 0) {
        float s = 0.f;
        for (int i = 0; i < 32; i++) s += gsh[i];
        gsum_sh = s;
    }
    __syncthreads();
    float denom = gsum_sh / 32.f + 1e-8f;
    int nh = (tid < 128) ? 5 : 4;
    for (int j = 0; j < nh; j++) {
        int h = tid + j * 256;
        float acc = 0.f;
        for (int idx = 0; idx < 32; idx++) {
            int p = idx >> 2, q = idx & 3;
            acc += out[OUT_MAJOR + ((size_t)(b * P_PAT + p) * 4 + q) * H_DIM + h] * gsh[idx];
        }
        float fin = (acc / 32.f) / denom;
        fr[h] = fin;
        out[OUT_FINAL + (size_t)b * H_DIM + h] = fin;
    }
    __syncthreads();
    int wid = tid >> 5, lane = tid & 31;
    for (int o = wid; o < E_DIM; o += 8) {
        float acc = 0.f;
        const float* wr = w1 + (size_t)o * H_DIM;
        for (int k = lane; k < H_DIM; k += 32) acc += wr[k] * fr[k];
        #pragma unroll
        for (int off = 16; off; off >>= 1) acc += __shfl_xor_sync(0xffffffffu, acc, off);
        if (lane == 0) hid[o] = gelu_exact(acc + b1[o]);
    }
    __syncthreads();
    for (int n = 0; n < NE; n++) {
        float v = hid[tid] * w2[n * E_DIM + tid] + hid[tid + 256] * w2[n * E_DIM + tid + 256];
        float tot = blockSum256(v);
        if (tid == 0) lg[n] = tot + b2[n];
    }
    __syncthreads();
    if (tid == 0) {
        float mx = -INFINITY;
        for (int n = 0; n < NE; n++) mx = fmaxf(mx, lg[n]);
        float sum = 0.f;
        float e[NE];
        for (int n = 0; n < NE; n++) { e[n] = expf(lg[n] - mx); sum += e[n]; }
        for (int n = 0; n < NE; n++) out[OUT_PREDS + b * NE + n] = e[n] / sum;
    }
}

extern "C" void kernel_launch(void* const* d_in, const int* in_sizes, int n_in,
                              void* d_out, int out_size) {
    const float* ov      = (const float*)d_in[0];
    const float* sig     = (const float*)d_in[1];
    const float* emo     = (const float*)d_in[2];
    const float* pool_w  = (const float*)d_in[3];
    const float* pool_b  = (const float*)d_in[4];
    const float* cls_w1  = (const float*)d_in[5];
    const float* cls_b1  = (const float*)d_in[6];
    const float* cls_w2  = (const float*)d_in[7];
    const float* cls_b2  = (const float*)d_in[8];
    const float* sig_w   = (const float*)d_in[9];
    const float* sig_b   = (const float*)d_in[10];
    const float* prm_w   = (const float*)d_in[11];
    const float* prm_b   = (const float*)d_in[12];
    const float* pred_w1 = (const float*)d_in[13];
    const float* pred_b1 = (const float*)d_in[14];
    const float* pred_w2 = (const float*)d_in[15];
    const float* pred_b2 = (const float*)d_in[16];
    const float* q_w     = (const float*)d_in[17];
    const float* q_b     = (const float*)d_in[18];
    const float* k_w     = (const float*)d_in[19];
    const float* k_b     = (const float*)d_in[20];
    float* out = (float*)d_out;

    cudaFuncSetAttribute(k_sig_mma, cudaFuncAttributeMaxDynamicSharedMemorySize, SM2_TOTAL);
    cudaFuncSetAttribute(k_tail, cudaFuncAttributeMaxDynamicSharedMemorySize, 73728);

    k_wsplit<<<1024, 256>>>(sig_w);                                    // 0
    k_pool<<<dim3(B_IMG, 9), 128>>>(ov, pool_w);                       // 1
    k_pre<<<dim3(B_IMG, NL), 256>>>(cls_w1, cls_b1, pool_b,
                                    cls_w2, cls_b2, emo, prm_w, prm_b); // 2
    k_sig_mma<<<dim3(12, T_TOK, NL * 2), 256, SM2_TOTAL>>>(sig, sig_b); // 3 <- ncu slot
    k_softmax_mean<<<T_TOK * NE, 256>>>();                              // 4
    k_tail<<<T_TOK, 256, 73728>>>(ov, q_w, q_b, k_w, k_b, out);         // 5
    k_finpred<<<B_IMG, 256>>>(pred_w1, pred_b1, pred_w2, pred_b2, out); // 6
}

// round 12
// speedup vs baseline: 1.0002x; 1.0002x over previous
#include <cuda_runtime.h>
#include <cuda_bf16.h>
#include <math.h>
#include <stdint.h>

#define T_TOK 64
#define S_SP  729
#define H_DIM 1152
#define E_DIM 512
#define NE    9
#define NL    4
#define B_IMG 8
#define P_PAT 8

#define OUT_MAJOR 0
#define OUT_FINAL (T_TOK * 4 * H_DIM)
#define OUT_PREDS (OUT_FINAL + B_IMG * H_DIM)

__device__ float g_poolpart[B_IMG * 9 * H_DIM];
__device__ float g_hidden [B_IMG * E_DIM];
__device__ float g_cls    [B_IMG * E_DIM];
__device__ float g_puv    [NL * 17 * E_DIM];
__device__ float g_prompts[NL * B_IMG * NE * E_DIM];
__device__ float g_part   [(size_t)NL * T_TOK * 2 * 10 * S_SP];
__device__ float g_meanatt[T_TOK * NE * S_SP];
__device__ float g_pes    [T_TOK * NE];
__device__ float g_gsig   [T_TOK * 4];
__device__ __align__(16) __nv_bfloat16 g_Whi[(size_t)NL * E_DIM * H_DIM];
__device__ __align__(16) __nv_bfloat16 g_Wlo[(size_t)NL * E_DIM * H_DIM];

__device__ __forceinline__ uint32_t smem_u32(const void* p) {
    uint32_t a;
    asm("{ .reg .u64 t; cvta.to.shared.u64 t, %1; cvt.u32.u64 %0, t; }" : "=r"(a) : "l"(p));
    return a;
}
__device__ __forceinline__ void cpasync16(uint32_t dst, const void* src) {
    asm volatile("cp.async.cg.shared.global [%0], [%1], 16;" :: "r"(dst), "l"(src));
}
#define CP_COMMIT() asm volatile("cp.async.commit_group;" ::: "memory")
#define CP_WAIT1()  asm volatile("cp.async.wait_group 1;" ::: "memory")

__device__ __forceinline__ float blockSum256(float v) {
    __shared__ float red[8];
    int lane = threadIdx.x & 31, wid = threadIdx.x >> 5;
    #pragma unroll
    for (int o = 16; o; o >>= 1) v += __shfl_xor_sync(0xffffffffu, v, o);
    if (lane == 0) red[wid] = v;
    __syncthreads();
    if (wid == 0) {
        float r = (lane < 8) ? red[lane] : 0.f;
        #pragma unroll
        for (int o = 4; o; o >>= 1) r += __shfl_xor_sync(0xffffffffu, r, o);
        if (lane == 0) red[0] = r;
    }
    __syncthreads();
    float r = red[0];
    __syncthreads();
    return r;
}
__device__ __forceinline__ float blockMax256(float v) {
    __shared__ float red[8];
    int lane = threadIdx.x & 31, wid = threadIdx.x >> 5;
    #pragma unroll
    for (int o = 16; o; o >>= 1) v = fmaxf(v, __shfl_xor_sync(0xffffffffu, v, o));
    if (lane == 0) red[wid] = v;
    __syncthreads();
    if (wid == 0) {
        float r = (lane < 8) ? red[lane] : -INFINITY;
        #pragma unroll
        for (int o = 4; o; o >>= 1) r = fmaxf(r, __shfl_xor_sync(0xffffffffu, r, o));
        if (lane == 0) red[0] = r;
    }
    __syncthreads();
    float r = red[0];
    __syncthreads();
    return r;
}
__device__ __forceinline__ float gelu_exact(float x) {
    return 0.5f * x * (1.0f + erff(x * 0.7071067811865475f));
}
__device__ __forceinline__ uint32_t pk2(__nv_bfloat16 a, __nv_bfloat16 b) {
    return ((uint32_t)__bfloat16_as_ushort(b) << 16) | (uint32_t)__bfloat16_as_ushort(a);
}
__device__ __forceinline__ void mma16816(float* d, const uint32_t* a, uint32_t b0, uint32_t b1) {
    asm volatile(
        "mma.sync.aligned.m16n8k16.row.col.f32.bf16.bf16.f32 "
        "{%0,%1,%2,%3}, {%4,%5,%6,%7}, {%8,%9}, {%0,%1,%2,%3};"
        : "+f"(d[0]), "+f"(d[1]), "+f"(d[2]), "+f"(d[3])
        : "r"(a[0]), "r"(a[1]), "r"(a[2]), "r"(a[3]), "r"(b0), "r"(b1));
}

__global__ void k_wsplit(const float* __restrict__ sw) {
    const size_t N = (size_t)NL * E_DIM * H_DIM;
    for (size_t i = (size_t)blockIdx.x * 256 + threadIdx.x; i < N; i += (size_t)gridDim.x * 256) {
        float w = sw[i];
        __nv_bfloat16 h = __float2bfloat16(w);
        g_Whi[i] = h;
        g_Wlo[i] = __float2bfloat16(w - __bfloat162float(h));
    }
}

__global__ void k_pool(const float* __restrict__ ov, const float* __restrict__ pw) {
    int b = blockIdx.x, sc = blockIdx.y, tid = threadIdx.x;
    float acc[9];
    #pragma unroll
    for (int j = 0; j < 9; j++) acc[j] = 0.f;
    const float* base = ov + (size_t)(b * P_PAT) * S_SP * H_DIM + (size_t)sc * 81 * H_DIM + tid;
    for (int s = 0; s < 81; s++) {
        float w = pw[sc * 81 + s];
        const float* p = base + (size_t)s * H_DIM;
        #pragma unroll
        for (int j = 0; j < 9; j++) acc[j] += w * p[j * 128];
    }
    #pragma unroll
    for (int j = 0; j < 9; j++)
        g_poolpart[((size_t)b * 9 + sc) * H_DIM + tid + j * 128] = acc[j];
}

__global__ void k_cls1(const float* __restrict__ w1, const float* __restrict__ b1,
                       const float* __restrict__ pb) {
    __shared__ float pr[B_IMG * H_DIM];
    int tid = threadIdx.x, wid = tid >> 5, lane = tid & 31;
    float pbias = pb[0];
    for (int idx = tid; idx < B_IMG * H_DIM; idx += 256) {
        int b = idx / H_DIM, h = idx - b * H_DIM;
        float s = pbias;
        #pragma unroll
        for (int sc = 0; sc < 9; sc++) s += g_poolpart[((size_t)b * 9 + sc) * H_DIM + h];
        pr[idx] = s;
    }
    __syncthreads();
    int o = blockIdx.x * 8 + wid;
    float acc[8];
    #pragma unroll
    for (int b = 0; b < 8; b++) acc[b] = 0.f;
    const float* wr = w1 + (size_t)o * H_DIM;
    for (int k = lane; k < H_DIM; k += 32) {
        float w = wr[k];
        #pragma unroll
        for (int b = 0; b < 8; b++) acc[b] += w * pr[b * H_DIM + k];
    }
    #pragma unroll
    for (int b = 0; b < 8; b++)
        #pragma unroll
        for (int off = 16; off; off >>= 1) acc[b] += __shfl_xor_sync(0xffffffffu, acc[b], off);
    if (lane == 0) {
        float bv = b1[o];
        #pragma unroll
        for (int b = 0; b < 8; b++) g_hidden[b * E_DIM + o] = gelu_exact(acc[b] + bv);
    }
}

__global__ void k_cls2(const float* __restrict__ w2, const float* __restrict__ b2) {
    __shared__ float hr[B_IMG * E_DIM];
    int tid = threadIdx.x, wid = tid >> 5, lane = tid & 31;
    for (int idx = tid; idx < B_IMG * E_DIM; idx += 256) hr[idx] = g_hidden[idx];
    __syncthreads();
    int o = blockIdx.x * 8 + wid;
    float acc[8];
    #pragma unroll
    for (int b = 0; b < 8; b++) acc[b] = 0.f;
    const float* wr = w2 + (size_t)o * E_DIM;
    for (int k = lane; k < E_DIM; k += 32) {
        float w = wr[k];
        #pragma unroll
        for (int b = 0; b < 8; b++) acc[b] += w * hr[b * E_DIM + k];
    }
    #pragma unroll
    for (int b = 0; b < 8; b++)
        #pragma unroll
        for (int off = 16; off; off >>= 1) acc[b] += __shfl_xor_sync(0xffffffffu, acc[b], off);
    if (lane == 0) {
        float bv = b2[o];
        #pragma unroll
        for (int b = 0; b < 8; b++) g_cls[b * E_DIM + o] = acc[b] + bv;
    }
}

__global__ void k_puv(const float* __restrict__ emo, const float* __restrict__ pw) {
    int oc = blockIdx.x, i = blockIdx.y;
    int tid = threadIdx.x, wid = tid >> 5, lane = tid & 31;
    __shared__ float es[NE * E_DIM];
    __shared__ float cs[B_IMG * E_DIM];
    for (int idx = tid; idx < NE * E_DIM; idx += 256) es[idx] = emo[idx];
    for (int idx = tid; idx < B_IMG * E_DIM; idx += 256) cs[idx] = g_cls[idx];
    __syncthreads();
    for (int oi = wid; oi < 32; oi += 8) {
        int o = oc * 32 + oi;
        const float* wr = pw + ((size_t)i * E_DIM + o) * 1024;
        float acc[17];
        #pragma unroll
        for (int j = 0; j < 17; j++) acc[j] = 0.f;
        for (int c = lane; c < 512; c += 32) {
            float w1 = wr[c];
            #pragma unroll
            for (int n = 0; n < NE; n++) acc[n] += w1 * es[n * 512 + c];
            float w2 = wr[512 + c];
            #pragma unroll
            for (int b = 0; b < B_IMG; b++) acc[9 + b] += w2 * cs[b * 512 + c];
        }
        #pragma unroll
        for (int j = 0; j < 17; j++)
            #pragma unroll
            for (int off = 16; off; off >>= 1) acc[j] += __shfl_xor_sync(0xffffffffu, acc[j], off);
        if (lane == 0) {
            #pragma unroll
            for (int j = 0; j < 17; j++) g_puv[((size_t)i * 17 + j) * 512 + o] = acc[j];
        }
    }
}

__global__ void k_prompts2(const float* __restrict__ pb) {
    int n = blockIdx.x, b = blockIdx.y, i = blockIdx.z;
    int tid = threadIdx.x;
    int o1 = tid, o2 = tid + 256;
    float r1 = g_puv[((size_t)i * 17 + n) * 512 + o1] + g_puv[((size_t)i * 17 + 9 + b) * 512 + o1]
             + pb[i * 512 + o1];
    float r2 = g_puv[((size_t)i * 17 + n) * 512 + o2] + g_puv[((size_t)i * 17 + 9 + b) * 512 + o2]
             + pb[i * 512 + o2];
    float nrm = blockSum256(r1 * r1 + r2 * r2);
    float inv = rsqrtf(nrm);
    size_t base = ((size_t)(i * B_IMG + b) * NE + n) * E_DIM;
    g_prompts[base + o1] = r1 * inv;
    g_prompts[base + o2] = r2 * inv;
}

// ======= sig GEMM: 512 threads (16 warps, 2m x 8n), 2 CTAs/SM, grid (12,64,8) =======
#define NCH 36
#define SM2_PSM   0
#define SM2_SBI   9216
#define SM2_RED   10240
#define SM2_A     12800
#define SM2_W     33280
#define SM2_YSM   12800
#define SM2_TOTAL 115200
#define Y_STR 260

__global__ void __launch_bounds__(512, 2)
k_sig_mma(const float* __restrict__ sig, const float* __restrict__ sb) {
    extern __shared__ char smem[];
    uint32_t sbase = smem_u32(smem);
    float* Psm = reinterpret_cast<float*>(smem + SM2_PSM);
    float* Sbi = reinterpret_cast<float*>(smem + SM2_SBI);
    float* red = reinterpret_cast<float*>(smem + SM2_RED);
    float* ysm = reinterpret_cast<float*>(smem + SM2_YSM);

    int tid = threadIdx.x, wid = tid >> 5, lane = tid & 31;
    int wm = wid >> 3, wn = wid & 7;           // warp tile: 32 rows x 32 cols
    int g = lane >> 2, tig = lane & 3;
    int s0 = blockIdx.x * 64;
    int t = blockIdx.y;
    int i = blockIdx.z >> 1, half = blockIdx.z & 1;
    int b = t >> 3;

    {
        size_t pbase = ((size_t)(i * B_IMG + b) * NE) * E_DIM + half * 256;
        for (int idx = tid; idx < NE * 256; idx += 512) {
            int n = idx >> 8, cc = idx & 255;
            Psm[idx] = g_prompts[pbase + (size_t)n * E_DIM + cc];
        }
        if (tid < 256) Sbi[tid] = sb[i * E_DIM + half * 256 + tid];
    }

    const float* Xbase = sig + ((size_t)(i * T_TOK + t) * S_SP) * H_DIM;
    const char* WH = reinterpret_cast<const char*>(g_Whi)
                   + ((size_t)i * E_DIM + half * 256) * H_DIM * 2;
    const char* WL = reinterpret_cast<const char*>(g_Wlo)
                   + ((size_t)i * E_DIM + half * 256) * H_DIM * 2;
    // W issue: thread (row = tid>>1, part = tid&1 selects hi/lo)
    const char* Wsel = (tid & 1) ? WL : WH;
    int wrow = tid >> 1;
    uint32_t wdst0 = sbase + SM2_W + (tid & 1) * 20480 + wrow * 80;

    float acc[2][4][4];
    #pragma unroll
    for (int mt = 0; mt < 2; mt++)
        #pragma unroll
        for (int nt = 0; nt < 4; nt++)
            #pragma unroll
            for (int c = 0; c < 4; c++) acc[mt][nt][c] = 0.f;

    int xrow = tid >> 2, xkc = tid & 3;
    int xs = s0 + xrow;
    const float* xptr = (tid < 256 && xs < S_SP) ? (Xbase + (size_t)xs * H_DIM + xkc * 8) : nullptr;
    char* adst = smem + SM2_A + xrow * 80 + xkc * 16;   // + buf*10240

#define ISSUE_W(CH, BUF) do { \
    const char* s_ = Wsel + ((size_t)wrow * H_DIM + (CH) * 32) * 2; \
    uint32_t d_ = wdst0 + (BUF) * 40960; \
    cpasync16(d_, s_); cpasync16(d_ + 16, s_ + 16); \
    cpasync16(d_ + 32, s_ + 32); cpasync16(d_ + 48, s_ + 48); \
} while (0)

#define STORE_A(CH, BUF) do { \
    if (tid < 256) { \
        float xv_[8]; \
        if (xptr) { \
            const float* p_ = xptr + (CH) * 32; \
            float4 f0_ = *reinterpret_cast<const float4*>(p_); \
            float4 f1_ = *reinterpret_cast<const float4*>(p_ + 4); \
            xv_[0]=f0_.x; xv_[1]=f0_.y; xv_[2]=f0_.z; xv_[3]=f0_.w; \
            xv_[4]=f1_.x; xv_[5]=f1_.y; xv_[6]=f1_.z; xv_[7]=f1_.w; \
        } else { \
            _Pragma("unroll") for (int j_ = 0; j_ < 8; j_++) xv_[j_] = 0.f; \
        } \
        uint32_t hq_[4], lq_[4]; \
        _Pragma("unroll") \
        for (int j_ = 0; j_ < 4; j_++) { \
            __nv_bfloat16 h0_ = __float2bfloat16(xv_[2*j_]); \
            __nv_bfloat16 h1_ = __float2bfloat16(xv_[2*j_+1]); \
            __nv_bfloat16 l0_ = __float2bfloat16(xv_[2*j_]   - __bfloat162float(h0_)); \
            __nv_bfloat16 l1_ = __float2bfloat16(xv_[2*j_+1] - __bfloat162float(h1_)); \
            hq_[j_] = pk2(h0_, h1_); \
            lq_[j_] = pk2(l0_, l1_); \
        } \
        char* aH = adst + (BUF) * 10240; \
        *reinterpret_cast<uint4*>(aH)        = make_uint4(hq_[0], hq_[1], hq_[2], hq_[3]); \
        *reinterpret_cast<uint4*>(aH + 5120) = make_uint4(lq_[0], lq_[1], lq_[2], lq_[3]); \
    } \
} while (0)

    ISSUE_W(0, 0); CP_COMMIT();
    ISSUE_W(1, 1); CP_COMMIT();
    STORE_A(0, 0);

    for (int ch = 0; ch < NCH; ch++) {
        int buf = ch & 1;
        if (ch > 0) STORE_A(ch, buf);
        CP_WAIT1();
        __syncthreads();

        const uint32_t* AH  = reinterpret_cast<const uint32_t*>(smem + SM2_A + buf * 10240);
        const uint32_t* AL  = AH + 1280;
        const uint32_t* WHs = reinterpret_cast<const uint32_t*>(smem + SM2_W + buf * 40960);
        const uint32_t* WLs = WHs + 5120;

        #pragma unroll
        for (int h = 0; h < 2; h++) {
            uint32_t ah[2][4], al[2][4];
            #pragma unroll
            for (int mt = 0; mt < 2; mt++) {
                int base = (wm * 32 + mt * 16 + g) * 20 + h * 8 + tig;
                ah[mt][0] = AH[base];     ah[mt][1] = AH[base + 160];
                ah[mt][2] = AH[base + 4]; ah[mt][3] = AH[base + 164];
                al[mt][0] = AL[base];     al[mt][1] = AL[base + 160];
                al[mt][2] = AL[base + 4]; al[mt][3] = AL[base + 164];
            }
            #pragma unroll
            for (int nt = 0; nt < 4; nt++) {
                int wb = (wn * 32 + nt * 8 + g) * 20 + h * 8 + tig;
                uint32_t b0h = WHs[wb], b1h = WHs[wb + 4];
                uint32_t b0l = WLs[wb], b1l = WLs[wb + 4];
                #pragma unroll
                for (int mt = 0; mt < 2; mt++) {
                    mma16816(acc[mt][nt], ah[mt], b0h, b1h);
                    mma16816(acc[mt][nt], ah[mt], b0l, b1l);
                    mma16816(acc[mt][nt], al[mt], b0h, b1h);
                }
            }
        }
        __syncthreads();
        if (ch + 2 < NCH) ISSUE_W(ch + 2, buf);
        CP_COMMIT();
    }

    // epilogue: bias + partial L2-norm + partial 9 prompt dots (single pass)
    #pragma unroll
    for (int mt = 0; mt < 2; mt++) {
        int row = wm * 32 + mt * 16 + g;
        #pragma unroll
        for (int nt = 0; nt < 4; nt++) {
            int col = wn * 32 + nt * 8 + tig * 2;
            float b0 = Sbi[col], b1 = Sbi[col + 1];
            *reinterpret_cast<float2*>(&ysm[row * Y_STR + col]) =
                make_float2(acc[mt][nt][0] + b0, acc[mt][nt][1] + b1);
            *reinterpret_cast<float2*>(&ysm[(row + 8) * Y_STR + col]) =
                make_float2(acc[mt][nt][2] + b0, acc[mt][nt][3] + b1);
        }
    }
    __syncthreads();
    for (int r4 = 0; r4 < 4; r4++) {
        int row = wid * 4 + r4;
        float v[10];
        #pragma unroll
        for (int j = 0; j < 10; j++) v[j] = 0.f;
        for (int cc = lane; cc < 256; cc += 32) {
            float y = ysm[row * Y_STR + cc];
            v[0] += y * y;
            #pragma unroll
            for (int n = 0; n < NE; n++) v[1 + n] += y * Psm[n * 256 + cc];
        }
        #pragma unroll
        for (int j = 0; j < 10; j++)
            #pragma unroll
            for (int off = 16; off; off >>= 1) v[j] += __shfl_xor_sync(0xffffffffu, v[j], off);
        if (lane == 0) {
            #pragma unroll
            for (int j = 0; j < 10; j++) red[row * 10 + j] = v[j];
        }
    }
    __syncthreads();

    if (tid < 64) {
        int s = s0 + tid;
        if (s < S_SP) {
            size_t base = ((((size_t)i * T_TOK + t) * 2 + half) * 10) * S_SP + s;
            #pragma unroll
            for (int j = 0; j < 10; j++)
                g_part[base + (size_t)j * S_SP] = red[tid * 10 + j];
        }
    }
#undef ISSUE_W
#undef STORE_A
}

// combine partials + softmax + level mean
__global__ void k_softmax_mean() {
    int tn = blockIdx.x;
    int t = tn / NE, n = tn % NE;
    int tid = threadIdx.x;
    float accm[3] = {0.f, 0.f, 0.f};
    for (int i = 0; i < NL; i++) {
        const float* p0 = g_part + ((((size_t)i * T_TOK + t) * 2 + 0) * 10) * S_SP;
        const float* p1 = g_part + ((((size_t)i * T_TOK + t) * 2 + 1) * 10) * S_SP;
        float x[3];
        float mx = -INFINITY;
        #pragma unroll
        for (int j = 0; j < 3; j++) {
            int s = tid + j * 256;
            if (s < S_SP) {
                float nsq = p0[s] + p1[s];
                float d = p0[(size_t)(1 + n) * S_SP + s] + p1[(size_t)(1 + n) * S_SP + s];
                x[j] = 100.f * d * rsqrtf(nsq);
            } else x[j] = -INFINITY;
            mx = fmaxf(mx, x[j]);
        }
        mx = blockMax256(mx);
        float lsum = 0.f;
        float e[3];
        #pragma unroll
        for (int j = 0; j < 3; j++) {
            int s = tid + j * 256;
            e[j] = (s < S_SP) ? expf(x[j] - mx) : 0.f;
            lsum += e[j];
        }
        float tot = blockSum256(lsum);
        float inv = 0.25f / tot;
        #pragma unroll
        for (int j = 0; j < 3; j++) accm[j] += e[j] * inv;
    }
    float psum = 0.f;
    size_t obase = ((size_t)t * NE + n) * S_SP;
    #pragma unroll
    for (int j = 0; j < 3; j++) {
        int s = tid + j * 256;
        if (s < S_SP) {
            g_meanatt[obase + s] = accm[j];
            psum += accm[j];
        }
    }
    float tot = blockSum256(psum);
    if (tid == 0) g_pes[t * NE + n] = tot / (float)S_SP;
}

__global__ void k_tail(const float* __restrict__ ov,
                       const float* __restrict__ qw, const float* __restrict__ qb,
                       const float* __restrict__ kw, const float* __restrict__ kb,
                       float* __restrict__ out) {
    extern __shared__ float S[];
    float* matt = S;
    float* sp   = S + 736;
    float* qkb  = S + 740;
    float* pmx  = S + 744;
    float* toks = S + 752;
    float* Qs   = toks + 4608;
    float* KQs  = Qs + 2048;
    float* law  = KQs + 4608;

    int t = blockIdx.x, tid = threadIdx.x;
    int wid = tid >> 5, lane = tid & 31;

    float bsum[4] = {0.f, 0.f, 0.f, 0.f};
    for (int s = tid; s < S_SP; s += 256) {
        float m = -INFINITY;
        #pragma unroll
        for (int n = 0; n < NE; n++)
            m = fmaxf(m, g_meanatt[((size_t)t * NE + n) * S_SP + s]);
        matt[s] = m;
        int r = s / 27, c = s - r * 27;
        bool r0 = r < 14, r1 = r >= 13, c0 = c < 14, c1 = c >= 13;
        if (r0 && c0) bsum[0] += m;
        if (r0 && c1) bsum[1] += m;
        if (r1 && c0) bsum[2] += m;
        if (r1 && c1) bsum[3] += m;
    }
    #pragma unroll
    for (int q = 0; q < 4; q++) {
        float tot = blockSum256(bsum[q]);
        if (tid == 0) sp[q] = tot / 196.f;
    }
    if (tid == 0) {
        float pm = -INFINITY;
        for (int n = 0; n < NE; n++) pm = fmaxf(pm, g_pes[t * NE + n]);
        pmx[0] = pm;
    }
    __syncthreads();
    if (tid < 4) g_gsig[t * 4 + tid] = sp[tid] * pmx[0];

    {
        int nh = (tid < 128) ? 5 : 4;
        float accT[5][4];
        #pragma unroll
        for (int j = 0; j < 5; j++)
            #pragma unroll
            for (int q = 0; q < 4; q++) accT[j][q] = 0.f;
        const float* obase = ov + ((size_t)t * S_SP) * H_DIM + tid;
        for (int s = 0; s < S_SP; s++) {
            float a = matt[s];
            int r = s / 27, c = s - r * 27;
            float w0 = (r < 14 && c < 14) ? a : 0.f;
            float w1 = (r < 14 && c >= 13) ? a : 0.f;
            float w2 = (r >= 13 && c < 14) ? a : 0.f;
            float w3 = (r >= 13 && c >= 13) ? a : 0.f;
            const float* p = obase + (size_t)s * H_DIM;
            #pragma unroll
            for (int j = 0; j < 5; j++) {
                if (j < nh) {
                    float v = p[j * 256];
                    accT[j][0] += v * w0;
                    accT[j][1] += v * w1;
                    accT[j][2] += v * w2;
                    accT[j][3] += v * w3;
                }
            }
        }
        for (int j = 0; j < nh; j++) {
            int h = tid + j * 256;
            #pragma unroll
            for (int q = 0; q < 4; q++)
                toks[q * H_DIM + h] = (accT[j][q] * (1.f / 196.f)) / (sp[q] + 1e-8f);
        }
    }
    __syncthreads();

    for (int o = wid; o < E_DIM; o += 8) {
        float acc[4] = {0.f, 0.f, 0.f, 0.f};
        const float* wr = qw + (size_t)o * H_DIM;
        for (int k = lane; k < H_DIM; k += 32) {
            float w = wr[k];
            #pragma unroll
            for (int q = 0; q < 4; q++) acc[q] += w * toks[q * H_DIM + k];
        }
        #pragma unroll
        for (int off = 16; off; off >>= 1)
            #pragma unroll
            for (int q = 0; q < 4; q++) acc[q] += __shfl_xor_sync(0xffffffffu, acc[q], off);
        if (lane == 0) {
            float bv = qb[o];
            #pragma unroll
            for (int q = 0; q < 4; q++) Qs[q * E_DIM + o] = acc[q] + bv;
        }
    }
    __syncthreads();
    if (wid < 4) {
        float acc = 0.f;
        for (int e = lane; e < E_DIM; e += 32) acc += Qs[wid * E_DIM + e] * kb[e];
        #pragma unroll
        for (int off = 16; off; off >>= 1) acc += __shfl_xor_sync(0xffffffffu, acc, off);
        if (lane == 0) qkb[wid] = acc;
    }
    __syncthreads();

    {
        float a[5][4];
        #pragma unroll
        for (int j = 0; j < 5; j++)
            #pragma unroll
            for (int q = 0; q < 4; q++) a[j][q] = 0.f;
        for (int e = 0; e < E_DIM; e++) {
            float q0 = Qs[e], q1 = Qs[512 + e], q2 = Qs[1024 + e], q3 = Qs[1536 + e];
            const float* kr = kw + (size_t)e * H_DIM;
            #pragma unroll
            for (int j = 0; j < 5; j++) {
                int h = j * 256 + tid;
                if (h < H_DIM) {
                    float kv = kr[h];
                    a[j][0] += kv * q0; a[j][1] += kv * q1;
                    a[j][2] += kv * q2; a[j][3] += kv * q3;
                }
            }
        }
        #pragma unroll
        for (int j = 0; j < 5; j++) {
            int h = j * 256 + tid;
            if (h < H_DIM) {
                #pragma unroll
                for (int q = 0; q < 4; q++) KQs[q * H_DIM + h] = a[j][q];
            }
        }
    }
    __syncthreads();

    const float RS = 0.04419417382415922f;
    for (int s = wid; s < S_SP; s += 8) {
        float acc[4] = {0.f, 0.f, 0.f, 0.f};
        const float* orow = ov + ((size_t)t * S_SP + s) * H_DIM;
        for (int h = lane; h < H_DIM; h += 32) {
            float vv = orow[h];
            #pragma unroll
            for (int q = 0; q < 4; q++) acc[q] += vv * KQs[q * H_DIM + h];
        }
        #pragma unroll
        for (int off = 16; off; off >>= 1)
            #pragma unroll
            for (int q = 0; q < 4; q++) acc[q] += __shfl_xor_sync(0xffffffffu, acc[q], off);
        if (lane == 0) {
            #pragma unroll
            for (int q = 0; q < 4; q++) law[q * S_SP + s] = (acc[q] + qkb[q]) * RS;
        }
    }
    __syncthreads();
    for (int q = 0; q < 4; q++) {
        float mx = -INFINITY;
        for (int s = tid; s < S_SP; s += 256) mx = fmaxf(mx, law[q * S_SP + s]);
        mx = blockMax256(mx);
        float lsum = 0.f;
        for (int s = tid; s < S_SP; s += 256) {
            float e = expf(law[q * S_SP + s] - mx);
            law[q * S_SP + s] = e;
            lsum += e;
        }
        float tot = blockSum256(lsum);
        float inv = 1.f / tot;
        for (int s = tid; s < S_SP; s += 256) law[q * S_SP + s] *= inv;
        __syncthreads();
    }

    {
        int nh = (tid < 128) ? 5 : 4;
        float macc[5][4];
        #pragma unroll
        for (int j = 0; j < 5; j++)
            #pragma unroll
            for (int q = 0; q < 4; q++) macc[j][q] = 0.f;
        const float* obase = ov + ((size_t)t * S_SP) * H_DIM + tid;
        for (int s = 0; s < S_SP; s++) {
            float a0 = law[0 * S_SP + s], a1 = law[1 * S_SP + s];
            float a2 = law[2 * S_SP + s], a3 = law[3 * S_SP + s];
            const float* p = obase + (size_t)s * H_DIM;
            #pragma unroll
            for (int j = 0; j < 5; j++) {
                if (j < nh) {
                    float v = p[j * 256];
                    macc[j][0] += a0 * v;
                    macc[j][1] += a1 * v;
                    macc[j][2] += a2 * v;
                    macc[j][3] += a3 * v;
                }
            }
        }
        for (int j = 0; j < nh; j++) {
            int h = tid + j * 256;
            #pragma unroll
            for (int q = 0; q < 4; q++)
                out[OUT_MAJOR + ((size_t)t * 4 + q) * H_DIM + h] = macc[j][q];
        }
    }
}

__global__ void k_finpred(const float* __restrict__ w1, const float* __restrict__ b1,
                          const float* __restrict__ w2, const float* __restrict__ b2,
                          float* __restrict__ out) {
    int b = blockIdx.x, tid = threadIdx.x;
    __shared__ float gsh[32];
    __shared__ float gsum_sh;
    __shared__ float fr[H_DIM];
    __shared__ float hid[E_DIM];
    __shared__ float lg[NE];
    if (tid < 32) {
        int p = tid >> 2, q = tid & 3;
        gsh[tid] = g_gsig[(b * P_PAT + p) * 4 + q];
    }
    __syncthreads();
    if (tid == 0) {
        float s = 0.f;
        for (int i = 0; i < 32; i++) s += gsh[i];
        gsum_sh = s;
    }
    __syncthreads();
    float denom = gsum_sh / 32.f + 1e-8f;
    int nh = (tid < 128) ? 5 : 4;
    for (int j = 0; j < nh; j++) {
        int h = tid + j * 256;
        float acc = 0.f;
        for (int idx = 0; idx < 32; idx++) {
            int p = idx >> 2, q = idx & 3;
            acc += out[OUT_MAJOR + ((size_t)(b * P_PAT + p) * 4 + q) * H_DIM + h] * gsh[idx];
        }
        float fin = (acc / 32.f) / denom;
        fr[h] = fin;
        out[OUT_FINAL + (size_t)b * H_DIM + h] = fin;
    }
    __syncthreads();
    int wid = tid >> 5, lane = tid & 31;
    for (int o = wid; o < E_DIM; o += 8) {
        float acc = 0.f;
        const float* wr = w1 + (size_t)o * H_DIM;
        for (int k = lane; k < H_DIM; k += 32) acc += wr[k] * fr[k];
        #pragma unroll
        for (int off = 16; off; off >>= 1) acc += __shfl_xor_sync(0xffffffffu, acc, off);
        if (lane == 0) hid[o] = gelu_exact(acc + b1[o]);
    }
    __syncthreads();
    for (int n = 0; n < NE; n++) {
        float v = hid[tid] * w2[n * E_DIM + tid] + hid[tid + 256] * w2[n * E_DIM + tid + 256];
        float tot = blockSum256(v);
        if (tid == 0) lg[n] = tot + b2[n];
    }
    __syncthreads();
    if (tid == 0) {
        float mx = -INFINITY;
        for (int n = 0; n < NE; n++) mx = fmaxf(mx, lg[n]);
        float sum = 0.f;
        float e[NE];
        for (int n = 0; n < NE; n++) { e[n] = expf(lg[n] - mx); sum += e[n]; }
        for (int n = 0; n < NE; n++) out[OUT_PREDS + b * NE + n] = e[n] / sum;
    }
}

extern "C" void kernel_launch(void* const* d_in, const int* in_sizes, int n_in,
                              void* d_out, int out_size) {
    const float* ov      = (const float*)d_in[0];
    const float* sig     = (const float*)d_in[1];
    const float* emo     = (const float*)d_in[2];
    const float* pool_w  = (const float*)d_in[3];
    const float* pool_b  = (const float*)d_in[4];
    const float* cls_w1  = (const float*)d_in[5];
    const float* cls_b1  = (const float*)d_in[6];
    const float* cls_w2  = (const float*)d_in[7];
    const float* cls_b2  = (const float*)d_in[8];
    const float* sig_w   = (const float*)d_in[9];
    const float* sig_b   = (const float*)d_in[10];
    const float* prm_w   = (const float*)d_in[11];
    const float* prm_b   = (const float*)d_in[12];
    const float* pred_w1 = (const float*)d_in[13];
    const float* pred_b1 = (const float*)d_in[14];
    const float* pred_w2 = (const float*)d_in[15];
    const float* pred_b2 = (const float*)d_in[16];
    const float* q_w     = (const float*)d_in[17];
    const float* q_b     = (const float*)d_in[18];
    const float* k_w     = (const float*)d_in[19];
    const float* k_b     = (const float*)d_in[20];
    float* out = (float*)d_out;

    cudaFuncSetAttribute(k_sig_mma, cudaFuncAttributeMaxDynamicSharedMemorySize, SM2_TOTAL);
    cudaFuncSetAttribute(k_tail, cudaFuncAttributeMaxDynamicSharedMemorySize, 61440);

    k_wsplit<<<1024, 256>>>(sig_w);
    k_pool<<<dim3(B_IMG, 9), 128>>>(ov, pool_w);
    k_cls1<<<64, 256>>>(cls_w1, cls_b1, pool_b);
    k_cls2<<<64, 256>>>(cls_w2, cls_b2);
    k_puv<<<dim3(16, NL), 256>>>(emo, prm_w);
    k_prompts2<<<dim3(NE, B_IMG, NL), 256>>>(prm_b);
    k_sig_mma<<<dim3(12, T_TOK, NL * 2), 512, SM2_TOTAL>>>(sig, sig_b);
    k_softmax_mean<<<T_TOK * NE, 256>>>();
    k_tail<<<T_TOK, 256, 61440>>>(ov, q_w, q_b, k_w, k_b, out);
    k_finpred<<<B_IMG, 256>>>(pred_w1, pred_b1, pred_w2, pred_b2, out);
}

// round 13
// speedup vs baseline: 1.3001x; 1.2999x over previous
#include <cuda_runtime.h>
#include <cuda_bf16.h>
#include <math.h>
#include <stdint.h>

#define T_TOK 64
#define S_SP  729
#define H_DIM 1152
#define E_DIM 512
#define NE    9
#define NL    4
#define B_IMG 8
#define P_PAT 8

#define OUT_MAJOR 0
#define OUT_FINAL (T_TOK * 4 * H_DIM)
#define OUT_PREDS (OUT_FINAL + B_IMG * H_DIM)

__device__ float g_poolpart[B_IMG * 9 * H_DIM];
__device__ float g_hidden [B_IMG * E_DIM];
__device__ float g_cls    [B_IMG * E_DIM];
__device__ float g_puv    [NL * 17 * E_DIM];
__device__ float g_prompts[NL * B_IMG * NE * E_DIM];
__device__ float g_part   [(size_t)NL * T_TOK * 2 * 10 * S_SP];
__device__ float g_meanatt[T_TOK * NE * S_SP];
__device__ float g_pes    [T_TOK * NE];
__device__ float g_gsig   [T_TOK * 4];
__device__ float g_wq     [T_TOK * 4 * 736];
__device__ float g_sp     [T_TOK * 4];
__device__ float g_tokens [T_TOK * 4 * H_DIM];
__device__ float g_Q      [T_TOK * 4 * E_DIM];
__device__ float g_KQ     [T_TOK * 4 * H_DIM];
__device__ float g_qkb    [T_TOK * 4];
__device__ float g_law    [T_TOK * 4 * 736];
__device__ __align__(16) __nv_bfloat16 g_Whi[(size_t)NL * E_DIM * H_DIM];
__device__ __align__(16) __nv_bfloat16 g_Wlo[(size_t)NL * E_DIM * H_DIM];

__device__ __forceinline__ uint32_t smem_u32(const void* p) {
    uint32_t a;
    asm("{ .reg .u64 t; cvta.to.shared.u64 t, %1; cvt.u32.u64 %0, t; }" : "=r"(a) : "l"(p));
    return a;
}
__device__ __forceinline__ void cpasync16(uint32_t dst, const void* src) {
    asm volatile("cp.async.cg.shared.global [%0], [%1], 16;" :: "r"(dst), "l"(src));
}
#define CP_COMMIT() asm volatile("cp.async.commit_group;" ::: "memory")
#define CP_WAIT1()  asm volatile("cp.async.wait_group 1;" ::: "memory")

__device__ __forceinline__ float blockSum256(float v) {
    __shared__ float red[8];
    int lane = threadIdx.x & 31, wid = threadIdx.x >> 5;
    #pragma unroll
    for (int o = 16; o; o >>= 1) v += __shfl_xor_sync(0xffffffffu, v, o);
    if (lane == 0) red[wid] = v;
    __syncthreads();
    if (wid == 0) {
        float r = (lane < 8) ? red[lane] : 0.f;
        #pragma unroll
        for (int o = 4; o; o >>= 1) r += __shfl_xor_sync(0xffffffffu, r, o);
        if (lane == 0) red[0] = r;
    }
    __syncthreads();
    float r = red[0];
    __syncthreads();
    return r;
}
__device__ __forceinline__ float blockMax256(float v) {
    __shared__ float red[8];
    int lane = threadIdx.x & 31, wid = threadIdx.x >> 5;
    #pragma unroll
    for (int o = 16; o; o >>= 1) v = fmaxf(v, __shfl_xor_sync(0xffffffffu, v, o));
    if (lane == 0) red[wid] = v;
    __syncthreads();
    if (wid == 0) {
        float r = (lane < 8) ? red[lane] : -INFINITY;
        #pragma unroll
        for (int o = 4; o; o >>= 1) r = fmaxf(r, __shfl_xor_sync(0xffffffffu, r, o));
        if (lane == 0) red[0] = r;
    }
    __syncthreads();
    float r = red[0];
    __syncthreads();
    return r;
}
__device__ __forceinline__ float gelu_exact(float x) {
    return 0.5f * x * (1.0f + erff(x * 0.7071067811865475f));
}
__device__ __forceinline__ uint32_t pk2(__nv_bfloat16 a, __nv_bfloat16 b) {
    return ((uint32_t)__bfloat16_as_ushort(b) << 16) | (uint32_t)__bfloat16_as_ushort(a);
}
__device__ __forceinline__ void mma16816(float* d, const uint32_t* a, uint32_t b0, uint32_t b1) {
    asm volatile(
        "mma.sync.aligned.m16n8k16.row.col.f32.bf16.bf16.f32 "
        "{%0,%1,%2,%3}, {%4,%5,%6,%7}, {%8,%9}, {%0,%1,%2,%3};"
        : "+f"(d[0]), "+f"(d[1]), "+f"(d[2]), "+f"(d[3])
        : "r"(a[0]), "r"(a[1]), "r"(a[2]), "r"(a[3]), "r"(b0), "r"(b1));
}

__global__ void k_wsplit(const float* __restrict__ sw) {
    const size_t N = (size_t)NL * E_DIM * H_DIM;
    for (size_t i = (size_t)blockIdx.x * 256 + threadIdx.x; i < N; i += (size_t)gridDim.x * 256) {
        float w = sw[i];
        __nv_bfloat16 h = __float2bfloat16(w);
        g_Whi[i] = h;
        g_Wlo[i] = __float2bfloat16(w - __bfloat162float(h));
    }
}

__global__ void k_pool(const float* __restrict__ ov, const float* __restrict__ pw) {
    int b = blockIdx.x, sc = blockIdx.y, tid = threadIdx.x;
    float acc[9];
    #pragma unroll
    for (int j = 0; j < 9; j++) acc[j] = 0.f;
    const float* base = ov + (size_t)(b * P_PAT) * S_SP * H_DIM + (size_t)sc * 81 * H_DIM + tid;
    for (int s = 0; s < 81; s++) {
        float w = pw[sc * 81 + s];
        const float* p = base + (size_t)s * H_DIM;
        #pragma unroll
        for (int j = 0; j < 9; j++) acc[j] += w * p[j * 128];
    }
    #pragma unroll
    for (int j = 0; j < 9; j++)
        g_poolpart[((size_t)b * 9 + sc) * H_DIM + tid + j * 128] = acc[j];
}

__global__ void k_cls1(const float* __restrict__ w1, const float* __restrict__ b1,
                       const float* __restrict__ pb) {
    __shared__ float pr[B_IMG * H_DIM];
    int tid = threadIdx.x, wid = tid >> 5, lane = tid & 31;
    float pbias = pb[0];
    for (int idx = tid; idx < B_IMG * H_DIM; idx += 256) {
        int b = idx / H_DIM, h = idx - b * H_DIM;
        float s = pbias;
        #pragma unroll
        for (int sc = 0; sc < 9; sc++) s += g_poolpart[((size_t)b * 9 + sc) * H_DIM + h];
        pr[idx] = s;
    }
    __syncthreads();
    int o = blockIdx.x * 8 + wid;
    float acc[8];
    #pragma unroll
    for (int b = 0; b < 8; b++) acc[b] = 0.f;
    const float* wr = w1 + (size_t)o * H_DIM;
    for (int k = lane; k < H_DIM; k += 32) {
        float w = wr[k];
        #pragma unroll
        for (int b = 0; b < 8; b++) acc[b] += w * pr[b * H_DIM + k];
    }
    #pragma unroll
    for (int b = 0; b < 8; b++)
        #pragma unroll
        for (int off = 16; off; off >>= 1) acc[b] += __shfl_xor_sync(0xffffffffu, acc[b], off);
    if (lane == 0) {
        float bv = b1[o];
        #pragma unroll
        for (int b = 0; b < 8; b++) g_hidden[b * E_DIM + o] = gelu_exact(acc[b] + bv);
    }
}

__global__ void k_cls2(const float* __restrict__ w2, const float* __restrict__ b2) {
    __shared__ float hr[B_IMG * E_DIM];
    int tid = threadIdx.x, wid = tid >> 5, lane = tid & 31;
    for (int idx = tid; idx < B_IMG * E_DIM; idx += 256) hr[idx] = g_hidden[idx];
    __syncthreads();
    int o = blockIdx.x * 8 + wid;
    float acc[8];
    #pragma unroll
    for (int b = 0; b < 8; b++) acc[b] = 0.f;
    const float* wr = w2 + (size_t)o * E_DIM;
    for (int k = lane; k < E_DIM; k += 32) {
        float w = wr[k];
        #pragma unroll
        for (int b = 0; b < 8; b++) acc[b] += w * hr[b * E_DIM + k];
    }
    #pragma unroll
    for (int b = 0; b < 8; b++)
        #pragma unroll
        for (int off = 16; off; off >>= 1) acc[b] += __shfl_xor_sync(0xffffffffu, acc[b], off);
    if (lane == 0) {
        float bv = b2[o];
        #pragma unroll
        for (int b = 0; b < 8; b++) g_cls[b * E_DIM + o] = acc[b] + bv;
    }
}

__global__ void k_puv(const float* __restrict__ emo, const float* __restrict__ pw) {
    int oc = blockIdx.x, i = blockIdx.y;
    int tid = threadIdx.x, wid = tid >> 5, lane = tid & 31;
    __shared__ float es[NE * E_DIM];
    __shared__ float cs[B_IMG * E_DIM];
    for (int idx = tid; idx < NE * E_DIM; idx += 256) es[idx] = emo[idx];
    for (int idx = tid; idx < B_IMG * E_DIM; idx += 256) cs[idx] = g_cls[idx];
    __syncthreads();
    for (int oi = wid; oi < 32; oi += 8) {
        int o = oc * 32 + oi;
        const float* wr = pw + ((size_t)i * E_DIM + o) * 1024;
        float acc[17];
        #pragma unroll
        for (int j = 0; j < 17; j++) acc[j] = 0.f;
        for (int c = lane; c < 512; c += 32) {
            float w1 = wr[c];
            #pragma unroll
            for (int n = 0; n < NE; n++) acc[n] += w1 * es[n * 512 + c];
            float w2 = wr[512 + c];
            #pragma unroll
            for (int b = 0; b < B_IMG; b++) acc[9 + b] += w2 * cs[b * 512 + c];
        }
        #pragma unroll
        for (int j = 0; j < 17; j++)
            #pragma unroll
            for (int off = 16; off; off >>= 1) acc[j] += __shfl_xor_sync(0xffffffffu, acc[j], off);
        if (lane == 0) {
            #pragma unroll
            for (int j = 0; j < 17; j++) g_puv[((size_t)i * 17 + j) * 512 + o] = acc[j];
        }
    }
}

__global__ void k_prompts2(const float* __restrict__ pb) {
    int n = blockIdx.x, b = blockIdx.y, i = blockIdx.z;
    int tid = threadIdx.x;
    int o1 = tid, o2 = tid + 256;
    float r1 = g_puv[((size_t)i * 17 + n) * 512 + o1] + g_puv[((size_t)i * 17 + 9 + b) * 512 + o1]
             + pb[i * 512 + o1];
    float r2 = g_puv[((size_t)i * 17 + n) * 512 + o2] + g_puv[((size_t)i * 17 + 9 + b) * 512 + o2]
             + pb[i * 512 + o2];
    float nrm = blockSum256(r1 * r1 + r2 * r2);
    float inv = rsqrtf(nrm);
    size_t base = ((size_t)(i * B_IMG + b) * NE + n) * E_DIM;
    g_prompts[base + o1] = r1 * inv;
    g_prompts[base + o2] = r2 * inv;
}

// ======= sig GEMM (R10 winner, byte-identical): grid (12,64,8), block 256, 2 CTA/SM =======
#define NCH 36
#define SM2_PSM   0
#define SM2_SBI   9216
#define SM2_RED   10240
#define SM2_A     12800
#define SM2_W     33280
#define SM2_YSM   12800
#define SM2_TOTAL 115200
#define Y_STR 260

__global__ void __launch_bounds__(256, 2)
k_sig_mma(const float* __restrict__ sig, const float* __restrict__ sb) {
    extern __shared__ char smem[];
    uint32_t sbase = smem_u32(smem);
    float* Psm = reinterpret_cast<float*>(smem + SM2_PSM);
    float* Sbi = reinterpret_cast<float*>(smem + SM2_SBI);
    float* red = reinterpret_cast<float*>(smem + SM2_RED);
    float* ysm = reinterpret_cast<float*>(smem + SM2_YSM);

    int tid = threadIdx.x, wid = tid >> 5, lane = tid & 31;
    int wm = wid >> 2, wn = wid & 3;
    int g = lane >> 2, tig = lane & 3;
    int s0 = blockIdx.x * 64;
    int t = blockIdx.y;
    int i = blockIdx.z >> 1, half = blockIdx.z & 1;
    int b = t >> 3;

    {
        size_t pbase = ((size_t)(i * B_IMG + b) * NE) * E_DIM + half * 256;
        for (int idx = tid; idx < NE * 256; idx += 256) {
            int n = idx >> 8, cc = idx & 255;
            Psm[idx] = g_prompts[pbase + (size_t)n * E_DIM + cc];
        }
        for (int idx = tid; idx < 256; idx += 256) Sbi[idx] = sb[i * E_DIM + half * 256 + idx];
        for (int idx = tid; idx < 640; idx += 256) red[idx] = 0.f;
    }

    const float* Xbase = sig + ((size_t)(i * T_TOK + t) * S_SP) * H_DIM;
    const char* WH = reinterpret_cast<const char*>(g_Whi)
                   + ((size_t)i * E_DIM + half * 256) * H_DIM * 2;
    const char* WL = reinterpret_cast<const char*>(g_Wlo)
                   + ((size_t)i * E_DIM + half * 256) * H_DIM * 2;

    float acc[2][8][4];
    #pragma unroll
    for (int mt = 0; mt < 2; mt++)
        #pragma unroll
        for (int nt = 0; nt < 8; nt++)
            #pragma unroll
            for (int c = 0; c < 4; c++) acc[mt][nt][c] = 0.f;

    int xrow = tid >> 2, xkc = tid & 3;
    int xs = s0 + xrow;
    const float* xptr = (xs < S_SP) ? (Xbase + (size_t)xs * H_DIM + xkc * 8) : nullptr;
    float xv[8];

#define ISSUE_W(CH, BUF) do { \
    uint32_t wHi = sbase + SM2_W + (BUF) * 40960; \
    int n_ = tid; \
    const char* sH = WH + ((size_t)n_ * H_DIM + (CH) * 32) * 2; \
    const char* sL = WL + ((size_t)n_ * H_DIM + (CH) * 32) * 2; \
    uint32_t dH = wHi + n_ * 80; \
    uint32_t dL = dH + 20480; \
    cpasync16(dH, sH); cpasync16(dH + 16, sH + 16); \
    cpasync16(dH + 32, sH + 32); cpasync16(dH + 48, sH + 48); \
    cpasync16(dL, sL); cpasync16(dL + 16, sL + 16); \
    cpasync16(dL + 32, sL + 32); cpasync16(dL + 48, sL + 48); \
} while (0)

#define LOAD_X(CH) do { \
    if (xptr) { \
        const float* p_ = xptr + (CH) * 32; \
        float4 f0_ = *reinterpret_cast<const float4*>(p_); \
        float4 f1_ = *reinterpret_cast<const float4*>(p_ + 4); \
        xv[0]=f0_.x; xv[1]=f0_.y; xv[2]=f0_.z; xv[3]=f0_.w; \
        xv[4]=f1_.x; xv[5]=f1_.y; xv[6]=f1_.z; xv[7]=f1_.w; \
    } else { \
        _Pragma("unroll") for (int j_ = 0; j_ < 8; j_++) xv[j_] = 0.f; \
    } \
} while (0)

#define STORE_A(BUF) do { \
    uint32_t hq_[4], lq_[4]; \
    _Pragma("unroll") \
    for (int j_ = 0; j_ < 4; j_++) { \
        __nv_bfloat16 h0_ = __float2bfloat16(xv[2*j_]); \
        __nv_bfloat16 h1_ = __float2bfloat16(xv[2*j_+1]); \
        __nv_bfloat16 l0_ = __float2bfloat16(xv[2*j_]   - __bfloat162float(h0_)); \
        __nv_bfloat16 l1_ = __float2bfloat16(xv[2*j_+1] - __bfloat162float(h1_)); \
        hq_[j_] = pk2(h0_, h1_); \
        lq_[j_] = pk2(l0_, l1_); \
    } \
    char* aH = smem + SM2_A + (BUF) * 10240 + xrow * 80 + xkc * 16; \
    *reinterpret_cast<uint4*>(aH)        = make_uint4(hq_[0], hq_[1], hq_[2], hq_[3]); \
    *reinterpret_cast<uint4*>(aH + 5120) = make_uint4(lq_[0], lq_[1], lq_[2], lq_[3]); \
} while (0)

    ISSUE_W(0, 0); CP_COMMIT();
    LOAD_X(0);
    ISSUE_W(1, 1); CP_COMMIT();
    STORE_A(0);
    LOAD_X(1);

    for (int ch = 0; ch < NCH; ch++) {
        int buf = ch & 1;
        if (ch > 0) {
            STORE_A(buf);
            if (ch + 1 < NCH) LOAD_X(ch + 1);
        }
        CP_WAIT1();
        __syncthreads();

        const uint32_t* AH  = reinterpret_cast<const uint32_t*>(smem + SM2_A + buf * 10240);
        const uint32_t* AL  = AH + 1280;
        const uint32_t* WHs = reinterpret_cast<const uint32_t*>(smem + SM2_W + buf * 40960);
        const uint32_t* WLs = WHs + 5120;

        #pragma unroll
        for (int h = 0; h < 2; h++) {
            uint32_t ah[2][4], al[2][4];
            #pragma unroll
            for (int mt = 0; mt < 2; mt++) {
                int base = (wm * 32 + mt * 16 + g) * 20 + h * 8 + tig;
                ah[mt][0] = AH[base];     ah[mt][1] = AH[base + 160];
                ah[mt][2] = AH[base + 4]; ah[mt][3] = AH[base + 164];
                al[mt][0] = AL[base];     al[mt][1] = AL[base + 160];
                al[mt][2] = AL[base + 4]; al[mt][3] = AL[base + 164];
            }
            #pragma unroll
            for (int nt = 0; nt < 8; nt++) {
                int wb = (wn * 64 + nt * 8 + g) * 20 + h * 8 + tig;
                uint32_t b0h = WHs[wb], b1h = WHs[wb + 4];
                uint32_t b0l = WLs[wb], b1l = WLs[wb + 4];
                #pragma unroll
                for (int mt = 0; mt < 2; mt++) {
                    mma16816(acc[mt][nt], ah[mt], b0h, b1h);
                    mma16816(acc[mt][nt], ah[mt], b0l, b1l);
                    mma16816(acc[mt][nt], al[mt], b0h, b1h);
                }
            }
        }
        __syncthreads();
        if (ch + 2 < NCH) ISSUE_W(ch + 2, buf);
        CP_COMMIT();
    }

    #pragma unroll
    for (int mt = 0; mt < 2; mt++) {
        int row = wm * 32 + mt * 16 + g;
        #pragma unroll
        for (int nt = 0; nt < 8; nt++) {
            int col = wn * 64 + nt * 8 + tig * 2;
            float b0 = Sbi[col], b1 = Sbi[col + 1];
            *reinterpret_cast<float2*>(&ysm[row * Y_STR + col]) =
                make_float2(acc[mt][nt][0] + b0, acc[mt][nt][1] + b1);
            *reinterpret_cast<float2*>(&ysm[(row + 8) * Y_STR + col]) =
                make_float2(acc[mt][nt][2] + b0, acc[mt][nt][3] + b1);
        }
    }
    __syncthreads();
    for (int r8 = 0; r8 < 8; r8++) {
        int row = wid * 8 + r8;
        float v[10];
        #pragma unroll
        for (int j = 0; j < 10; j++) v[j] = 0.f;
        for (int cc = lane; cc < 256; cc += 32) {
            float y = ysm[row * Y_STR + cc];
            v[0] += y * y;
            #pragma unroll
            for (int n = 0; n < NE; n++) v[1 + n] += y * Psm[n * 256 + cc];
        }
        #pragma unroll
        for (int j = 0; j < 10; j++)
            #pragma unroll
            for (int off = 16; off; off >>= 1) v[j] += __shfl_xor_sync(0xffffffffu, v[j], off);
        if (lane == 0) {
            #pragma unroll
            for (int j = 0; j < 10; j++) red[row * 10 + j] = v[j];
        }
    }
    __syncthreads();

    if (tid < 64) {
        int s = s0 + tid;
        if (s < S_SP) {
            size_t base = ((((size_t)i * T_TOK + t) * 2 + half) * 10) * S_SP + s;
            #pragma unroll
            for (int j = 0; j < 10; j++)
                g_part[base + (size_t)j * S_SP] = red[tid * 10 + j];
        }
    }
#undef ISSUE_W
#undef LOAD_X
#undef STORE_A
}

__global__ void k_softmax_mean() {
    int tn = blockIdx.x;
    int t = tn / NE, n = tn % NE;
    int tid = threadIdx.x;
    float accm[3] = {0.f, 0.f, 0.f};
    for (int i = 0; i < NL; i++) {
        const float* p0 = g_part + ((((size_t)i * T_TOK + t) * 2 + 0) * 10) * S_SP;
        const float* p1 = g_part + ((((size_t)i * T_TOK + t) * 2 + 1) * 10) * S_SP;
        float x[3];
        float mx = -INFINITY;
        #pragma unroll
        for (int j = 0; j < 3; j++) {
            int s = tid + j * 256;
            if (s < S_SP) {
                float nsq = p0[s] + p1[s];
                float d = p0[(size_t)(1 + n) * S_SP + s] + p1[(size_t)(1 + n) * S_SP + s];
                x[j] = 100.f * d * rsqrtf(nsq);
            } else x[j] = -INFINITY;
            mx = fmaxf(mx, x[j]);
        }
        mx = blockMax256(mx);
        float lsum = 0.f;
        float e[3];
        #pragma unroll
        for (int j = 0; j < 3; j++) {
            int s = tid + j * 256;
            e[j] = (s < S_SP) ? expf(x[j] - mx) : 0.f;
            lsum += e[j];
        }
        float tot = blockSum256(lsum);
        float inv = 0.25f / tot;
        #pragma unroll
        for (int j = 0; j < 3; j++) accm[j] += e[j] * inv;
    }
    float psum = 0.f;
    size_t obase = ((size_t)t * NE + n) * S_SP;
    #pragma unroll
    for (int j = 0; j < 3; j++) {
        int s = tid + j * 256;
        if (s < S_SP) {
            g_meanatt[obase + s] = accm[j];
            psum += accm[j];
        }
    }
    float tot = blockSum256(psum);
    if (tid == 0) g_pes[t * NE + n] = tot / (float)S_SP;
}

// ---- tail stage 1: masked quadrant weight planes + sp + gsig, grid 64 ----
__global__ void k_matt() {
    int t = blockIdx.x, tid = threadIdx.x;
    float bsum[4] = {0.f, 0.f, 0.f, 0.f};
    #pragma unroll
    for (int j = 0; j < 3; j++) {
        int s = tid + j * 256;
        if (s < S_SP) {
            float m = -INFINITY;
            #pragma unroll
            for (int n = 0; n < NE; n++)
                m = fmaxf(m, g_meanatt[((size_t)t * NE + n) * S_SP + s]);
            int r = s / 27, c = s - r * 27;
            float w0 = (r < 14 && c < 14) ? m : 0.f;
            float w1 = (r < 14 && c >= 13) ? m : 0.f;
            float w2 = (r >= 13 && c < 14) ? m : 0.f;
            float w3 = (r >= 13 && c >= 13) ? m : 0.f;
            size_t wb = (size_t)t * 4 * 736 + s;
            g_wq[wb] = w0;
            g_wq[wb + 736] = w1;
            g_wq[wb + 1472] = w2;
            g_wq[wb + 2208] = w3;
            bsum[0] += w0; bsum[1] += w1; bsum[2] += w2; bsum[3] += w3;
        }
    }
    #pragma unroll
    for (int q = 0; q < 4; q++) {
        float tot = blockSum256(bsum[q]);
        if (tid == 0) g_sp[t * 4 + q] = tot / 196.f;
    }
    if (tid == 0) {
        float pm = -INFINITY;
        for (int n = 0; n < NE; n++) pm = fmaxf(pm, g_pes[t * NE + n]);
        float sp0 = g_sp[t * 4 + 0], sp1 = g_sp[t * 4 + 1];
        float sp2 = g_sp[t * 4 + 2], sp3 = g_sp[t * 4 + 3];
        g_gsig[t * 4 + 0] = sp0 * pm;
        g_gsig[t * 4 + 1] = sp1 * pm;
        g_gsig[t * 4 + 2] = sp2 * pm;
        g_gsig[t * 4 + 3] = sp3 * pm;
    }
}

// ---- tail stage 2: tokens, grid (64, 9), block 128 ----
__global__ void k_tok(const float* __restrict__ ov) {
    __shared__ float wqs[4 * 736];
    __shared__ float sps[4];
    int t = blockIdx.x, hc = blockIdx.y, tid = threadIdx.x;
    for (int idx = tid; idx < 4 * 736; idx += 128) wqs[idx] = g_wq[(size_t)t * 4 * 736 + idx];
    if (tid < 4) sps[tid] = g_sp[t * 4 + tid];
    __syncthreads();
    int h = hc * 128 + tid;
    float a0 = 0.f, a1 = 0.f, a2 = 0.f, a3 = 0.f;
    const float* base = ov + ((size_t)t * S_SP) * H_DIM + h;
    for (int s = 0; s < S_SP; s++) {
        float v = base[(size_t)s * H_DIM];
        a0 += v * wqs[s];
        a1 += v * wqs[736 + s];
        a2 += v * wqs[1472 + s];
        a3 += v * wqs[2208 + s];
    }
    g_tokens[((size_t)t * 4 + 0) * H_DIM + h] = (a0 * (1.f / 196.f)) / (sps[0] + 1e-8f);
    g_tokens[((size_t)t * 4 + 1) * H_DIM + h] = (a1 * (1.f / 196.f)) / (sps[1] + 1e-8f);
    g_tokens[((size_t)t * 4 + 2) * H_DIM + h] = (a2 * (1.f / 196.f)) / (sps[2] + 1e-8f);
    g_tokens[((size_t)t * 4 + 3) * H_DIM + h] = (a3 * (1.f / 196.f)) / (sps[3] + 1e-8f);
}

// ---- tail stage 3: Q projection, grid 64 ----
__global__ void k_qproj(const float* __restrict__ qw, const float* __restrict__ qb) {
    int t = blockIdx.x, tid = threadIdx.x;
    __shared__ float toks[4 * H_DIM];
    for (int idx = tid; idx < 4 * H_DIM; idx += 256) toks[idx] = g_tokens[(size_t)t * 4 * H_DIM + idx];
    __syncthreads();
    int wid = tid >> 5, lane = tid & 31;
    for (int o = wid; o < E_DIM; o += 8) {
        float acc[4] = {0.f, 0.f, 0.f, 0.f};
        const float* wr = qw + (size_t)o * H_DIM;
        for (int k = lane; k < H_DIM; k += 32) {
            float w = wr[k];
            #pragma unroll
            for (int q = 0; q < 4; q++) acc[q] += w * toks[q * H_DIM + k];
        }
        #pragma unroll
        for (int off = 16; off; off >>= 1)
            #pragma unroll
            for (int q = 0; q < 4; q++) acc[q] += __shfl_xor_sync(0xffffffffu, acc[q], off);
        if (lane == 0) {
            float bv = qb[o];
            #pragma unroll
            for (int q = 0; q < 4; q++) g_Q[((size_t)t * 4 + q) * E_DIM + o] = acc[q] + bv;
        }
    }
}

// ---- tail stage 4: KQ = k_w^T Q, grid (64, 9) ----
__global__ void k_kq(const float* __restrict__ kw, const float* __restrict__ kb) {
    int t = blockIdx.x, hc = blockIdx.y;
    int tid = threadIdx.x;
    __shared__ float Qs[4 * E_DIM];
    for (int idx = tid; idx < 4 * E_DIM; idx += 256) Qs[idx] = g_Q[(size_t)t * 4 * E_DIM + idx];
    __syncthreads();
    int h = hc * 128 + (tid >> 1);
    int q0 = (tid & 1) * 2;
    float a0 = 0.f, a1 = 0.f;
    const float* kcol = kw + h;
    for (int e = 0; e < E_DIM; e++) {
        float kv = kcol[(size_t)e * H_DIM];
        a0 += kv * Qs[(q0 + 0) * E_DIM + e];
        a1 += kv * Qs[(q0 + 1) * E_DIM + e];
    }
    g_KQ[((size_t)t * 4 + q0 + 0) * H_DIM + h] = a0;
    g_KQ[((size_t)t * 4 + q0 + 1) * H_DIM + h] = a1;

    if (hc == 0 && tid < 128) {
        int wid = tid >> 5, lane = tid & 31;
        float acc = 0.f;
        for (int e = lane; e < E_DIM; e += 32) acc += Qs[wid * E_DIM + e] * kb[e];
        #pragma unroll
        for (int off = 16; off; off >>= 1) acc += __shfl_xor_sync(0xffffffffu, acc, off);
        if (lane == 0) g_qkb[t * 4 + wid] = acc;
    }
}

// ---- tail stage 5: logits, grid (64, 6), block 128 ----
__global__ void k_logits(const float* __restrict__ ov) {
    __shared__ float KQs[4 * H_DIM];
    __shared__ float qkbs[4];
    int t = blockIdx.x, sc = blockIdx.y, tid = threadIdx.x;
    int wid = tid >> 5, lane = tid & 31;
    for (int idx = tid; idx < 4 * H_DIM; idx += 128) KQs[idx] = g_KQ[(size_t)t * 4 * H_DIM + idx];
    if (tid < 4) qkbs[tid] = g_qkb[t * 4 + tid];
    __syncthreads();
    const float RS = 0.04419417382415922f;
    for (int s = sc * 128 + wid; s < min(sc * 128 + 128, S_SP); s += 4) {
        float acc[4] = {0.f, 0.f, 0.f, 0.f};
        const float* orow = ov + ((size_t)t * S_SP + s) * H_DIM;
        for (int h = lane; h < H_DIM; h += 32) {
            float vv = orow[h];
            #pragma unroll
            for (int q = 0; q < 4; q++) acc[q] += vv * KQs[q * H_DIM + h];
        }
        #pragma unroll
        for (int off = 16; off; off >>= 1)
            #pragma unroll
            for (int q = 0; q < 4; q++) acc[q] += __shfl_xor_sync(0xffffffffu, acc[q], off);
        if (lane == 0) {
            #pragma unroll
            for (int q = 0; q < 4; q++)
                g_law[((size_t)t * 4 + q) * 736 + s] = (acc[q] + qkbs[q]) * RS;
        }
    }
}

// ---- tail stage 6: 4 softmaxes per t, grid 64 ----
__global__ void k_soft4() {
    int t = blockIdx.x, tid = threadIdx.x;
    for (int q = 0; q < 4; q++) {
        float* L = g_law + ((size_t)t * 4 + q) * 736;
        float x[3];
        float mx = -INFINITY;
        #pragma unroll
        for (int j = 0; j < 3; j++) {
            int s = tid + j * 256;
            x[j] = (s < S_SP) ? L[s] : -INFINITY;
            mx = fmaxf(mx, x[j]);
        }
        mx = blockMax256(mx);
        float lsum = 0.f;
        float e[3];
        #pragma unroll
        for (int j = 0; j < 3; j++) {
            int s = tid + j * 256;
            e[j] = (s < S_SP) ? expf(x[j] - mx) : 0.f;
            lsum += e[j];
        }
        float tot = blockSum256(lsum);
        float inv = 1.f / tot;
        #pragma unroll
        for (int j = 0; j < 3; j++) {
            int s = tid + j * 256;
            if (s < S_SP) L[s] = e[j] * inv;
        }
    }
}

// ---- tail stage 7: major = aw @ ov, grid (64, 9), block 128 ----
__global__ void k_major(const float* __restrict__ ov, float* __restrict__ out) {
    __shared__ float law[4 * 736];
    int t = blockIdx.x, hc = blockIdx.y, tid = threadIdx.x;
    for (int idx = tid; idx < 4 * 736; idx += 128) {
        int q = idx / 736, s = idx - q * 736;
        law[idx] = (s < S_SP) ? g_law[((size_t)t * 4 + q) * 736 + s] : 0.f;
    }
    __syncthreads();
    int h = hc * 128 + tid;
    float a0 = 0.f, a1 = 0.f, a2 = 0.f, a3 = 0.f;
    const float* base = ov + ((size_t)t * S_SP) * H_DIM + h;
    for (int s = 0; s < S_SP; s++) {
        float v = base[(size_t)s * H_DIM];
        a0 += v * law[s];
        a1 += v * law[736 + s];
        a2 += v * law[1472 + s];
        a3 += v * law[2208 + s];
    }
    out[OUT_MAJOR + ((size_t)t * 4 + 0) * H_DIM + h] = a0;
    out[OUT_MAJOR + ((size_t)t * 4 + 1) * H_DIM + h] = a1;
    out[OUT_MAJOR + ((size_t)t * 4 + 2) * H_DIM + h] = a2;
    out[OUT_MAJOR + ((size_t)t * 4 + 3) * H_DIM + h] = a3;
}

__global__ void k_finpred(const float* __restrict__ w1, const float* __restrict__ b1,
                          const float* __restrict__ w2, const float* __restrict__ b2,
                          float* __restrict__ out) {
    int b = blockIdx.x, tid = threadIdx.x;
    __shared__ float gsh[32];
    __shared__ float gsum_sh;
    __shared__ float fr[H_DIM];
    __shared__ float hid[E_DIM];
    __shared__ float lg[NE];
    if (tid < 32) {
        int p = tid >> 2, q = tid & 3;
        gsh[tid] = g_gsig[(b * P_PAT + p) * 4 + q];
    }
    __syncthreads();
    if (tid == 0) {
        float s = 0.f;
        for (int i = 0; i < 32; i++) s += gsh[i];
        gsum_sh = s;
    }
    __syncthreads();
    float denom = gsum_sh / 32.f + 1e-8f;
    int nh = (tid < 128) ? 5 : 4;
    for (int j = 0; j < nh; j++) {
        int h = tid + j * 256;
        float acc = 0.f;
        for (int idx = 0; idx < 32; idx++) {
            int p = idx >> 2, q = idx & 3;
            acc += out[OUT_MAJOR + ((size_t)(b * P_PAT + p) * 4 + q) * H_DIM + h] * gsh[idx];
        }
        float fin = (acc / 32.f) / denom;
        fr[h] = fin;
        out[OUT_FINAL + (size_t)b * H_DIM + h] = fin;
    }
    __syncthreads();
    int wid = tid >> 5, lane = tid & 31;
    for (int o = wid; o < E_DIM; o += 8) {
        float acc = 0.f;
        const float* wr = w1 + (size_t)o * H_DIM;
        for (int k = lane; k < H_DIM; k += 32) acc += wr[k] * fr[k];
        #pragma unroll
        for (int off = 16; off; off >>= 1) acc += __shfl_xor_sync(0xffffffffu, acc, off);
        if (lane == 0) hid[o] = gelu_exact(acc + b1[o]);
    }
    __syncthreads();
    for (int n = 0; n < NE; n++) {
        float v = hid[tid] * w2[n * E_DIM + tid] + hid[tid + 256] * w2[n * E_DIM + tid + 256];
        float tot = blockSum256(v);
        if (tid == 0) lg[n] = tot + b2[n];
    }
    __syncthreads();
    if (tid == 0) {
        float mx = -INFINITY;
        for (int n = 0; n < NE; n++) mx = fmaxf(mx, lg[n]);
        float sum = 0.f;
        float e[NE];
        for (int n = 0; n < NE; n++) { e[n] = expf(lg[n] - mx); sum += e[n]; }
        for (int n = 0; n < NE; n++) out[OUT_PREDS + b * NE + n] = e[n] / sum;
    }
}

extern "C" void kernel_launch(void* const* d_in, const int* in_sizes, int n_in,
                              void* d_out, int out_size) {
    const float* ov      = (const float*)d_in[0];
    const float* sig     = (const float*)d_in[1];
    const float* emo     = (const float*)d_in[2];
    const float* pool_w  = (const float*)d_in[3];
    const float* pool_b  = (const float*)d_in[4];
    const float* cls_w1  = (const float*)d_in[5];
    const float* cls_b1  = (const float*)d_in[6];
    const float* cls_w2  = (const float*)d_in[7];
    const float* cls_b2  = (const float*)d_in[8];
    const float* sig_w   = (const float*)d_in[9];
    const float* sig_b   = (const float*)d_in[10];
    const float* prm_w   = (const float*)d_in[11];
    const float* prm_b   = (const float*)d_in[12];
    const float* pred_w1 = (const float*)d_in[13];
    const float* pred_b1 = (const float*)d_in[14];
    const float* pred_w2 = (const float*)d_in[15];
    const float* pred_b2 = (const float*)d_in[16];
    const float* q_w     = (const float*)d_in[17];
    const float* q_b     = (const float*)d_in[18];
    const float* k_w     = (const float*)d_in[19];
    const float* k_b     = (const float*)d_in[20];
    float* out = (float*)d_out;

    cudaFuncSetAttribute(k_sig_mma, cudaFuncAttributeMaxDynamicSharedMemorySize, SM2_TOTAL);

    k_wsplit<<<1024, 256>>>(sig_w);
    k_pool<<<dim3(B_IMG, 9), 128>>>(ov, pool_w);
    k_cls1<<<64, 256>>>(cls_w1, cls_b1, pool_b);
    k_cls2<<<64, 256>>>(cls_w2, cls_b2);
    k_puv<<<dim3(16, NL), 256>>>(emo, prm_w);
    k_prompts2<<<dim3(NE, B_IMG, NL), 256>>>(prm_b);
    k_sig_mma<<<dim3(12, T_TOK, NL * 2), 256, SM2_TOTAL>>>(sig, sig_b);
    k_softmax_mean<<<T_TOK * NE, 256>>>();
    k_matt<<<T_TOK, 256>>>();
    k_tok<<<dim3(T_TOK, 9), 128>>>(ov);
    k_qproj<<<T_TOK, 256>>>(q_w, q_b);
    k_kq<<<dim3(T_TOK, 9), 256>>>(k_w, k_b);
    k_logits<<<dim3(T_TOK, 6), 128>>>(ov);
    k_soft4<<<T_TOK, 256>>>();
    k_major<<<dim3(T_TOK, 9), 128>>>(ov, out);
    k_finpred<<<B_IMG, 256>>>(pred_w1, pred_b1, pred_w2, pred_b2, out);
}

// round 14
// speedup vs baseline: 1.4660x; 1.1275x over previous
#include <cuda_runtime.h>
#include <cuda_fp16.h>
#include <math.h>
#include <stdint.h>

#define T_TOK 64
#define S_SP  729
#define H_DIM 1152
#define E_DIM 512
#define NE    9
#define NL    4
#define B_IMG 8
#define P_PAT 8

#define OUT_MAJOR 0
#define OUT_FINAL (T_TOK * 4 * H_DIM)
#define OUT_PREDS (OUT_FINAL + B_IMG * H_DIM)

__device__ float g_poolpart[B_IMG * 9 * H_DIM];
__device__ float g_hidden [B_IMG * E_DIM];
__device__ float g_cls    [B_IMG * E_DIM];
__device__ float g_puv    [NL * 17 * E_DIM];
__device__ float g_prompts[NL * B_IMG * NE * E_DIM];
__device__ float g_part   [(size_t)NL * T_TOK * 2 * 10 * S_SP];
__device__ float g_meanatt[T_TOK * NE * S_SP];
__device__ float g_pes    [T_TOK * NE];
__device__ float g_gsig   [T_TOK * 4];
__device__ float g_wq     [T_TOK * 4 * 736];
__device__ float g_sp     [T_TOK * 4];
__device__ float g_tokens [T_TOK * 4 * H_DIM];
__device__ float g_Q      [T_TOK * 4 * E_DIM];
__device__ float g_KQ     [T_TOK * 4 * H_DIM];
__device__ float g_qkb    [T_TOK * 4];
__device__ float g_law    [T_TOK * 4 * 736];
__device__ __align__(16) __half g_Whi[(size_t)NL * E_DIM * H_DIM];
__device__ __align__(16) __half g_Wlo[(size_t)NL * E_DIM * H_DIM];

#define WSCALE 32.0f

__device__ __forceinline__ uint32_t smem_u32(const void* p) {
    uint32_t a;
    asm("{ .reg .u64 t; cvta.to.shared.u64 t, %1; cvt.u32.u64 %0, t; }" : "=r"(a) : "l"(p));
    return a;
}
__device__ __forceinline__ void cpasync16(uint32_t dst, const void* src) {
    asm volatile("cp.async.cg.shared.global [%0], [%1], 16;" :: "r"(dst), "l"(src));
}
#define CP_COMMIT() asm volatile("cp.async.commit_group;" ::: "memory")
#define CP_WAIT1()  asm volatile("cp.async.wait_group 1;" ::: "memory")

__device__ __forceinline__ float blockSum256(float v) {
    __shared__ float red[8];
    int lane = threadIdx.x & 31, wid = threadIdx.x >> 5;
    #pragma unroll
    for (int o = 16; o; o >>= 1) v += __shfl_xor_sync(0xffffffffu, v, o);
    if (lane == 0) red[wid] = v;
    __syncthreads();
    if (wid == 0) {
        float r = (lane < 8) ? red[lane] : 0.f;
        #pragma unroll
        for (int o = 4; o; o >>= 1) r += __shfl_xor_sync(0xffffffffu, r, o);
        if (lane == 0) red[0] = r;
    }
    __syncthreads();
    float r = red[0];
    __syncthreads();
    return r;
}
__device__ __forceinline__ float blockMax256(float v) {
    __shared__ float red[8];
    int lane = threadIdx.x & 31, wid = threadIdx.x >> 5;
    #pragma unroll
    for (int o = 16; o; o >>= 1) v = fmaxf(v, __shfl_xor_sync(0xffffffffu, v, o));
    if (lane == 0) red[wid] = v;
    __syncthreads();
    if (wid == 0) {
        float r = (lane < 8) ? red[lane] : -INFINITY;
        #pragma unroll
        for (int o = 4; o; o >>= 1) r = fmaxf(r, __shfl_xor_sync(0xffffffffu, r, o));
        if (lane == 0) red[0] = r;
    }
    __syncthreads();
    float r = red[0];
    __syncthreads();
    return r;
}
__device__ __forceinline__ float gelu_exact(float x) {
    return 0.5f * x * (1.0f + erff(x * 0.7071067811865475f));
}
__device__ __forceinline__ uint32_t pk2h(__half a, __half b) {
    return ((uint32_t)__half_as_ushort(b) << 16) | (uint32_t)__half_as_ushort(a);
}
__device__ __forceinline__ void mmaf16(float* d, const uint32_t* a, uint32_t b0, uint32_t b1) {
    asm volatile(
        "mma.sync.aligned.m16n8k16.row.col.f32.f16.f16.f32 "
        "{%0,%1,%2,%3}, {%4,%5,%6,%7}, {%8,%9}, {%0,%1,%2,%3};"
        : "+f"(d[0]), "+f"(d[1]), "+f"(d[2]), "+f"(d[3])
        : "r"(a[0]), "r"(a[1]), "r"(a[2]), "r"(a[3]), "r"(b0), "r"(b1));
}

__global__ void k_wsplit(const float* __restrict__ sw) {
    const size_t N = (size_t)NL * E_DIM * H_DIM;
    for (size_t i = (size_t)blockIdx.x * 256 + threadIdx.x; i < N; i += (size_t)gridDim.x * 256) {
        float w = sw[i] * WSCALE;
        __half h = __float2half(w);
        g_Whi[i] = h;
        g_Wlo[i] = __float2half(w - __half2float(h));
    }
}

__global__ void k_pool(const float* __restrict__ ov, const float* __restrict__ pw) {
    int b = blockIdx.x, sc = blockIdx.y, tid = threadIdx.x;
    float acc[9];
    #pragma unroll
    for (int j = 0; j < 9; j++) acc[j] = 0.f;
    const float* base = ov + (size_t)(b * P_PAT) * S_SP * H_DIM + (size_t)sc * 81 * H_DIM + tid;
    for (int s = 0; s < 81; s++) {
        float w = pw[sc * 81 + s];
        const float* p = base + (size_t)s * H_DIM;
        #pragma unroll
        for (int j = 0; j < 9; j++) acc[j] += w * p[j * 128];
    }
    #pragma unroll
    for (int j = 0; j < 9; j++)
        g_poolpart[((size_t)b * 9 + sc) * H_DIM + tid + j * 128] = acc[j];
}

__global__ void k_cls1(const float* __restrict__ w1, const float* __restrict__ b1,
                       const float* __restrict__ pb) {
    __shared__ float pr[B_IMG * H_DIM];
    int tid = threadIdx.x, wid = tid >> 5, lane = tid & 31;
    float pbias = pb[0];
    for (int idx = tid; idx < B_IMG * H_DIM; idx += 256) {
        int b = idx / H_DIM, h = idx - b * H_DIM;
        float s = pbias;
        #pragma unroll
        for (int sc = 0; sc < 9; sc++) s += g_poolpart[((size_t)b * 9 + sc) * H_DIM + h];
        pr[idx] = s;
    }
    __syncthreads();
    int o = blockIdx.x * 8 + wid;
    float acc[8];
    #pragma unroll
    for (int b = 0; b < 8; b++) acc[b] = 0.f;
    const float* wr = w1 + (size_t)o * H_DIM;
    for (int k = lane; k < H_DIM; k += 32) {
        float w = wr[k];
        #pragma unroll
        for (int b = 0; b < 8; b++) acc[b] += w * pr[b * H_DIM + k];
    }
    #pragma unroll
    for (int b = 0; b < 8; b++)
        #pragma unroll
        for (int off = 16; off; off >>= 1) acc[b] += __shfl_xor_sync(0xffffffffu, acc[b], off);
    if (lane == 0) {
        float bv = b1[o];
        #pragma unroll
        for (int b = 0; b < 8; b++) g_hidden[b * E_DIM + o] = gelu_exact(acc[b] + bv);
    }
}

__global__ void k_cls2(const float* __restrict__ w2, const float* __restrict__ b2) {
    __shared__ float hr[B_IMG * E_DIM];
    int tid = threadIdx.x, wid = tid >> 5, lane = tid & 31;
    for (int idx = tid; idx < B_IMG * E_DIM; idx += 256) hr[idx] = g_hidden[idx];
    __syncthreads();
    int o = blockIdx.x * 8 + wid;
    float acc[8];
    #pragma unroll
    for (int b = 0; b < 8; b++) acc[b] = 0.f;
    const float* wr = w2 + (size_t)o * E_DIM;
    for (int k = lane; k < E_DIM; k += 32) {
        float w = wr[k];
        #pragma unroll
        for (int b = 0; b < 8; b++) acc[b] += w * hr[b * E_DIM + k];
    }
    #pragma unroll
    for (int b = 0; b < 8; b++)
        #pragma unroll
        for (int off = 16; off; off >>= 1) acc[b] += __shfl_xor_sync(0xffffffffu, acc[b], off);
    if (lane == 0) {
        float bv = b2[o];
        #pragma unroll
        for (int b = 0; b < 8; b++) g_cls[b * E_DIM + o] = acc[b] + bv;
    }
}

__global__ void k_puv(const float* __restrict__ emo, const float* __restrict__ pw) {
    int oc = blockIdx.x, i = blockIdx.y;
    int tid = threadIdx.x, wid = tid >> 5, lane = tid & 31;
    __shared__ float es[NE * E_DIM];
    __shared__ float cs[B_IMG * E_DIM];
    for (int idx = tid; idx < NE * E_DIM; idx += 256) es[idx] = emo[idx];
    for (int idx = tid; idx < B_IMG * E_DIM; idx += 256) cs[idx] = g_cls[idx];
    __syncthreads();
    for (int oi = wid; oi < 32; oi += 8) {
        int o = oc * 32 + oi;
        const float* wr = pw + ((size_t)i * E_DIM + o) * 1024;
        float acc[17];
        #pragma unroll
        for (int j = 0; j < 17; j++) acc[j] = 0.f;
        for (int c = lane; c < 512; c += 32) {
            float w1 = wr[c];
            #pragma unroll
            for (int n = 0; n < NE; n++) acc[n] += w1 * es[n * 512 + c];
            float w2 = wr[512 + c];
            #pragma unroll
            for (int b = 0; b < B_IMG; b++) acc[9 + b] += w2 * cs[b * 512 + c];
        }
        #pragma unroll
        for (int j = 0; j < 17; j++)
            #pragma unroll
            for (int off = 16; off; off >>= 1) acc[j] += __shfl_xor_sync(0xffffffffu, acc[j], off);
        if (lane == 0) {
            #pragma unroll
            for (int j = 0; j < 17; j++) g_puv[((size_t)i * 17 + j) * 512 + o] = acc[j];
        }
    }
}

__global__ void k_prompts2(const float* __restrict__ pb) {
    int n = blockIdx.x, b = blockIdx.y, i = blockIdx.z;
    int tid = threadIdx.x;
    int o1 = tid, o2 = tid + 256;
    float r1 = g_puv[((size_t)i * 17 + n) * 512 + o1] + g_puv[((size_t)i * 17 + 9 + b) * 512 + o1]
             + pb[i * 512 + o1];
    float r2 = g_puv[((size_t)i * 17 + n) * 512 + o2] + g_puv[((size_t)i * 17 + 9 + b) * 512 + o2]
             + pb[i * 512 + o2];
    float nrm = blockSum256(r1 * r1 + r2 * r2);
    float inv = rsqrtf(nrm);
    size_t base = ((size_t)(i * B_IMG + b) * NE + n) * E_DIM;
    g_prompts[base + o1] = r1 * inv;
    g_prompts[base + o2] = r2 * inv;
}

// ======= sig GEMM: fp16 scaled 2-product, grid (12,64,8), block 256, 2 CTA/SM =======
#define NCH 36
#define SM2_PSM   0          // 9216
#define SM2_SBI   9216       // 1024
#define SM2_RED   10240      // 2560
#define SM2_A     12800      // 2 bufs x 5120 = 10240
#define SM2_W     23040      // 2 bufs x (hi 20480 + lo 20480) = 81920
#define SM2_YSM   12800      // union: 64*260*4 = 66560 (ends 79360)
#define SM2_TOTAL 104960
#define Y_STR 260

__global__ void __launch_bounds__(256, 2)
k_sig_mma(const float* __restrict__ sig, const float* __restrict__ sb) {
    extern __shared__ char smem[];
    uint32_t sbase = smem_u32(smem);
    float* Psm = reinterpret_cast<float*>(smem + SM2_PSM);
    float* Sbi = reinterpret_cast<float*>(smem + SM2_SBI);
    float* red = reinterpret_cast<float*>(smem + SM2_RED);
    float* ysm = reinterpret_cast<float*>(smem + SM2_YSM);

    int tid = threadIdx.x, wid = tid >> 5, lane = tid & 31;
    int wm = wid >> 2, wn = wid & 3;
    int g = lane >> 2, tig = lane & 3;
    int s0 = blockIdx.x * 64;
    int t = blockIdx.y;
    int i = blockIdx.z >> 1, half = blockIdx.z & 1;
    int b = t >> 3;

    {
        size_t pbase = ((size_t)(i * B_IMG + b) * NE) * E_DIM + half * 256;
        for (int idx = tid; idx < NE * 256; idx += 256) {
            int n = idx >> 8, cc = idx & 255;
            Psm[idx] = g_prompts[pbase + (size_t)n * E_DIM + cc];
        }
        for (int idx = tid; idx < 256; idx += 256)
            Sbi[idx] = WSCALE * sb[i * E_DIM + half * 256 + idx];
        for (int idx = tid; idx < 640; idx += 256) red[idx] = 0.f;
    }

    const float* Xbase = sig + ((size_t)(i * T_TOK + t) * S_SP) * H_DIM;
    const char* WH = reinterpret_cast<const char*>(g_Whi)
                   + ((size_t)i * E_DIM + half * 256) * H_DIM * 2;
    const char* WL = reinterpret_cast<const char*>(g_Wlo)
                   + ((size_t)i * E_DIM + half * 256) * H_DIM * 2;

    float acc[2][8][4];
    #pragma unroll
    for (int mt = 0; mt < 2; mt++)
        #pragma unroll
        for (int nt = 0; nt < 8; nt++)
            #pragma unroll
            for (int c = 0; c < 4; c++) acc[mt][nt][c] = 0.f;

    int xrow = tid >> 2, xkc = tid & 3;
    int xs = s0 + xrow;
    const float* xptr = (xs < S_SP) ? (Xbase + (size_t)xs * H_DIM + xkc * 8) : nullptr;
    float xv[8];

#define ISSUE_W(CH, BUF) do { \
    uint32_t wHi = sbase + SM2_W + (BUF) * 40960; \
    int n_ = tid; \
    const char* sH = WH + ((size_t)n_ * H_DIM + (CH) * 32) * 2; \
    const char* sL = WL + ((size_t)n_ * H_DIM + (CH) * 32) * 2; \
    uint32_t dH = wHi + n_ * 80; \
    uint32_t dL = dH + 20480; \
    cpasync16(dH, sH); cpasync16(dH + 16, sH + 16); \
    cpasync16(dH + 32, sH + 32); cpasync16(dH + 48, sH + 48); \
    cpasync16(dL, sL); cpasync16(dL + 16, sL + 16); \
    cpasync16(dL + 32, sL + 32); cpasync16(dL + 48, sL + 48); \
} while (0)

#define LOAD_X(CH) do { \
    if (xptr) { \
        const float* p_ = xptr + (CH) * 32; \
        float4 f0_ = *reinterpret_cast<const float4*>(p_); \
        float4 f1_ = *reinterpret_cast<const float4*>(p_ + 4); \
        xv[0]=f0_.x; xv[1]=f0_.y; xv[2]=f0_.z; xv[3]=f0_.w; \
        xv[4]=f1_.x; xv[5]=f1_.y; xv[6]=f1_.z; xv[7]=f1_.w; \
    } else { \
        _Pragma("unroll") for (int j_ = 0; j_ < 8; j_++) xv[j_] = 0.f; \
    } \
} while (0)

#define STORE_A(BUF) do { \
    uint32_t hq_[4]; \
    _Pragma("unroll") \
    for (int j_ = 0; j_ < 4; j_++) \
        hq_[j_] = pk2h(__float2half(xv[2*j_]), __float2half(xv[2*j_+1])); \
    char* aH = smem + SM2_A + (BUF) * 5120 + xrow * 80 + xkc * 16; \
    *reinterpret_cast<uint4*>(aH) = make_uint4(hq_[0], hq_[1], hq_[2], hq_[3]); \
} while (0)

    ISSUE_W(0, 0); CP_COMMIT();
    LOAD_X(0);
    ISSUE_W(1, 1); CP_COMMIT();
    STORE_A(0);
    LOAD_X(1);

    for (int ch = 0; ch < NCH; ch++) {
        int buf = ch & 1;
        if (ch > 0) {
            STORE_A(buf);
            if (ch + 1 < NCH) LOAD_X(ch + 1);
        }
        CP_WAIT1();
        __syncthreads();

        const uint32_t* AH  = reinterpret_cast<const uint32_t*>(smem + SM2_A + buf * 5120);
        const uint32_t* WHs = reinterpret_cast<const uint32_t*>(smem + SM2_W + buf * 40960);
        const uint32_t* WLs = WHs + 5120;

        #pragma unroll
        for (int h = 0; h < 2; h++) {
            uint32_t ah[2][4];
            #pragma unroll
            for (int mt = 0; mt < 2; mt++) {
                int base = (wm * 32 + mt * 16 + g) * 20 + h * 8 + tig;
                ah[mt][0] = AH[base];     ah[mt][1] = AH[base + 160];
                ah[mt][2] = AH[base + 4]; ah[mt][3] = AH[base + 164];
            }
            #pragma unroll
            for (int nt = 0; nt < 8; nt++) {
                int wb = (wn * 64 + nt * 8 + g) * 20 + h * 8 + tig;
                uint32_t b0h = WHs[wb], b1h = WHs[wb + 4];
                uint32_t b0l = WLs[wb], b1l = WLs[wb + 4];
                #pragma unroll
                for (int mt = 0; mt < 2; mt++) {
                    mmaf16(acc[mt][nt], ah[mt], b0h, b1h);
                    mmaf16(acc[mt][nt], ah[mt], b0l, b1l);
                }
            }
        }
        __syncthreads();
        if (ch + 2 < NCH) ISSUE_W(ch + 2, buf);
        CP_COMMIT();
    }

    // epilogue (scale-invariant): bias(x32) + partial L2-norm + partial prompt dots
    #pragma unroll
    for (int mt = 0; mt < 2; mt++) {
        int row = wm * 32 + mt * 16 + g;
        #pragma unroll
        for (int nt = 0; nt < 8; nt++) {
            int col = wn * 64 + nt * 8 + tig * 2;
            float b0 = Sbi[col], b1 = Sbi[col + 1];
            *reinterpret_cast<float2*>(&ysm[row * Y_STR + col]) =
                make_float2(acc[mt][nt][0] + b0, acc[mt][nt][1] + b1);
            *reinterpret_cast<float2*>(&ysm[(row + 8) * Y_STR + col]) =
                make_float2(acc[mt][nt][2] + b0, acc[mt][nt][3] + b1);
        }
    }
    __syncthreads();
    for (int r8 = 0; r8 < 8; r8++) {
        int row = wid * 8 + r8;
        float v[10];
        #pragma unroll
        for (int j = 0; j < 10; j++) v[j] = 0.f;
        for (int cc = lane; cc < 256; cc += 32) {
            float y = ysm[row * Y_STR + cc];
            v[0] += y * y;
            #pragma unroll
            for (int n = 0; n < NE; n++) v[1 + n] += y * Psm[n * 256 + cc];
        }
        #pragma unroll
        for (int j = 0; j < 10; j++)
            #pragma unroll
            for (int off = 16; off; off >>= 1) v[j] += __shfl_xor_sync(0xffffffffu, v[j], off);
        if (lane == 0) {
            #pragma unroll
            for (int j = 0; j < 10; j++) red[row * 10 + j] = v[j];
        }
    }
    __syncthreads();

    if (tid < 64) {
        int s = s0 + tid;
        if (s < S_SP) {
            size_t base = ((((size_t)i * T_TOK + t) * 2 + half) * 10) * S_SP + s;
            #pragma unroll
            for (int j = 0; j < 10; j++)
                g_part[base + (size_t)j * S_SP] = red[tid * 10 + j];
        }
    }
#undef ISSUE_W
#undef LOAD_X
#undef STORE_A
}

__global__ void k_softmax_mean() {
    int tn = blockIdx.x;
    int t = tn / NE, n = tn % NE;
    int tid = threadIdx.x;
    float accm[3] = {0.f, 0.f, 0.f};
    for (int i = 0; i < NL; i++) {
        const float* p0 = g_part + ((((size_t)i * T_TOK + t) * 2 + 0) * 10) * S_SP;
        const float* p1 = g_part + ((((size_t)i * T_TOK + t) * 2 + 1) * 10) * S_SP;
        float x[3];
        float mx = -INFINITY;
        #pragma unroll
        for (int j = 0; j < 3; j++) {
            int s = tid + j * 256;
            if (s < S_SP) {
                float nsq = p0[s] + p1[s];
                float d = p0[(size_t)(1 + n) * S_SP + s] + p1[(size_t)(1 + n) * S_SP + s];
                x[j] = 100.f * d * rsqrtf(nsq);
            } else x[j] = -INFINITY;
            mx = fmaxf(mx, x[j]);
        }
        mx = blockMax256(mx);
        float lsum = 0.f;
        float e[3];
        #pragma unroll
        for (int j = 0; j < 3; j++) {
            int s = tid + j * 256;
            e[j] = (s < S_SP) ? expf(x[j] - mx) : 0.f;
            lsum += e[j];
        }
        float tot = blockSum256(lsum);
        float inv = 0.25f / tot;
        #pragma unroll
        for (int j = 0; j < 3; j++) accm[j] += e[j] * inv;
    }
    float psum = 0.f;
    size_t obase = ((size_t)t * NE + n) * S_SP;
    #pragma unroll
    for (int j = 0; j < 3; j++) {
        int s = tid + j * 256;
        if (s < S_SP) {
            g_meanatt[obase + s] = accm[j];
            psum += accm[j];
        }
    }
    float tot = blockSum256(psum);
    if (tid == 0) g_pes[t * NE + n] = tot / (float)S_SP;
}

__global__ void k_matt() {
    int t = blockIdx.x, tid = threadIdx.x;
    float bsum[4] = {0.f, 0.f, 0.f, 0.f};
    #pragma unroll
    for (int j = 0; j < 3; j++) {
        int s = tid + j * 256;
        if (s < S_SP) {
            float m = -INFINITY;
            #pragma unroll
            for (int n = 0; n < NE; n++)
                m = fmaxf(m, g_meanatt[((size_t)t * NE + n) * S_SP + s]);
            int r = s / 27, c = s - r * 27;
            float w0 = (r < 14 && c < 14) ? m : 0.f;
            float w1 = (r < 14 && c >= 13) ? m : 0.f;
            float w2 = (r >= 13 && c < 14) ? m : 0.f;
            float w3 = (r >= 13 && c >= 13) ? m : 0.f;
            size_t wb = (size_t)t * 4 * 736 + s;
            g_wq[wb] = w0;
            g_wq[wb + 736] = w1;
            g_wq[wb + 1472] = w2;
            g_wq[wb + 2208] = w3;
            bsum[0] += w0; bsum[1] += w1; bsum[2] += w2; bsum[3] += w3;
        }
    }
    #pragma unroll
    for (int q = 0; q < 4; q++) {
        float tot = blockSum256(bsum[q]);
        if (tid == 0) g_sp[t * 4 + q] = tot / 196.f;
    }
    if (tid == 0) {
        float pm = -INFINITY;
        for (int n = 0; n < NE; n++) pm = fmaxf(pm, g_pes[t * NE + n]);
        g_gsig[t * 4 + 0] = g_sp[t * 4 + 0] * pm;
        g_gsig[t * 4 + 1] = g_sp[t * 4 + 1] * pm;
        g_gsig[t * 4 + 2] = g_sp[t * 4 + 2] * pm;
        g_gsig[t * 4 + 3] = g_sp[t * 4 + 3] * pm;
    }
}

__global__ void k_tok(const float* __restrict__ ov) {
    __shared__ float wqs[4 * 736];
    __shared__ float sps[4];
    int t = blockIdx.x, hc = blockIdx.y, tid = threadIdx.x;
    for (int idx = tid; idx < 4 * 736; idx += 128) wqs[idx] = g_wq[(size_t)t * 4 * 736 + idx];
    if (tid < 4) sps[tid] = g_sp[t * 4 + tid];
    __syncthreads();
    int h = hc * 128 + tid;
    float a0 = 0.f, a1 = 0.f, a2 = 0.f, a3 = 0.f;
    const float* base = ov + ((size_t)t * S_SP) * H_DIM + h;
    for (int s = 0; s < S_SP; s++) {
        float v = base[(size_t)s * H_DIM];
        a0 += v * wqs[s];
        a1 += v * wqs[736 + s];
        a2 += v * wqs[1472 + s];
        a3 += v * wqs[2208 + s];
    }
    g_tokens[((size_t)t * 4 + 0) * H_DIM + h] = (a0 * (1.f / 196.f)) / (sps[0] + 1e-8f);
    g_tokens[((size_t)t * 4 + 1) * H_DIM + h] = (a1 * (1.f / 196.f)) / (sps[1] + 1e-8f);
    g_tokens[((size_t)t * 4 + 2) * H_DIM + h] = (a2 * (1.f / 196.f)) / (sps[2] + 1e-8f);
    g_tokens[((size_t)t * 4 + 3) * H_DIM + h] = (a3 * (1.f / 196.f)) / (sps[3] + 1e-8f);
}

__global__ void k_qproj(const float* __restrict__ qw, const float* __restrict__ qb) {
    int t = blockIdx.x, tid = threadIdx.x;
    __shared__ float toks[4 * H_DIM];
    for (int idx = tid; idx < 4 * H_DIM; idx += 256) toks[idx] = g_tokens[(size_t)t * 4 * H_DIM + idx];
    __syncthreads();
    int wid = tid >> 5, lane = tid & 31;
    for (int o = wid; o < E_DIM; o += 8) {
        float acc[4] = {0.f, 0.f, 0.f, 0.f};
        const float* wr = qw + (size_t)o * H_DIM;
        for (int k = lane; k < H_DIM; k += 32) {
            float w = wr[k];
            #pragma unroll
            for (int q = 0; q < 4; q++) acc[q] += w * toks[q * H_DIM + k];
        }
        #pragma unroll
        for (int off = 16; off; off >>= 1)
            #pragma unroll
            for (int q = 0; q < 4; q++) acc[q] += __shfl_xor_sync(0xffffffffu, acc[q], off);
        if (lane == 0) {
            float bv = qb[o];
            #pragma unroll
            for (int q = 0; q < 4; q++) g_Q[((size_t)t * 4 + q) * E_DIM + o] = acc[q] + bv;
        }
    }
}

__global__ void k_kq(const float* __restrict__ kw, const float* __restrict__ kb) {
    int t = blockIdx.x, hc = blockIdx.y;
    int tid = threadIdx.x;
    __shared__ float Qs[4 * E_DIM];
    for (int idx = tid; idx < 4 * E_DIM; idx += 256) Qs[idx] = g_Q[(size_t)t * 4 * E_DIM + idx];
    __syncthreads();
    int h = hc * 128 + (tid >> 1);
    int q0 = (tid & 1) * 2;
    float a0 = 0.f, a1 = 0.f;
    const float* kcol = kw + h;
    for (int e = 0; e < E_DIM; e++) {
        float kv = kcol[(size_t)e * H_DIM];
        a0 += kv * Qs[(q0 + 0) * E_DIM + e];
        a1 += kv * Qs[(q0 + 1) * E_DIM + e];
    }
    g_KQ[((size_t)t * 4 + q0 + 0) * H_DIM + h] = a0;
    g_KQ[((size_t)t * 4 + q0 + 1) * H_DIM + h] = a1;

    if (hc == 0 && tid < 128) {
        int wid = tid >> 5, lane = tid & 31;
        float acc = 0.f;
        for (int e = lane; e < E_DIM; e += 32) acc += Qs[wid * E_DIM + e] * kb[e];
        #pragma unroll
        for (int off = 16; off; off >>= 1) acc += __shfl_xor_sync(0xffffffffu, acc, off);
        if (lane == 0) g_qkb[t * 4 + wid] = acc;
    }
}

__global__ void k_logits(const float* __restrict__ ov) {
    __shared__ float KQs[4 * H_DIM];
    __shared__ float qkbs[4];
    int t = blockIdx.x, sc = blockIdx.y, tid = threadIdx.x;
    int wid = tid >> 5, lane = tid & 31;
    for (int idx = tid; idx < 4 * H_DIM; idx += 128) KQs[idx] = g_KQ[(size_t)t * 4 * H_DIM + idx];
    if (tid < 4) qkbs[tid] = g_qkb[t * 4 + tid];
    __syncthreads();
    const float RS = 0.04419417382415922f;
    for (int s = sc * 128 + wid; s < min(sc * 128 + 128, S_SP); s += 4) {
        float acc[4] = {0.f, 0.f, 0.f, 0.f};
        const float* orow = ov + ((size_t)t * S_SP + s) * H_DIM;
        for (int h = lane; h < H_DIM; h += 32) {
            float vv = orow[h];
            #pragma unroll
            for (int q = 0; q < 4; q++) acc[q] += vv * KQs[q * H_DIM + h];
        }
        #pragma unroll
        for (int off = 16; off; off >>= 1)
            #pragma unroll
            for (int q = 0; q < 4; q++) acc[q] += __shfl_xor_sync(0xffffffffu, acc[q], off);
        if (lane == 0) {
            #pragma unroll
            for (int q = 0; q < 4; q++)
                g_law[((size_t)t * 4 + q) * 736 + s] = (acc[q] + qkbs[q]) * RS;
        }
    }
}

__global__ void k_soft4() {
    int t = blockIdx.x, tid = threadIdx.x;
    for (int q = 0; q < 4; q++) {
        float* L = g_law + ((size_t)t * 4 + q) * 736;
        float x[3];
        float mx = -INFINITY;
        #pragma unroll
        for (int j = 0; j < 3; j++) {
            int s = tid + j * 256;
            x[j] = (s < S_SP) ? L[s] : -INFINITY;
            mx = fmaxf(mx, x[j]);
        }
        mx = blockMax256(mx);
        float lsum = 0.f;
        float e[3];
        #pragma unroll
        for (int j = 0; j < 3; j++) {
            int s = tid + j * 256;
            e[j] = (s < S_SP) ? expf(x[j] - mx) : 0.f;
            lsum += e[j];
        }
        float tot = blockSum256(lsum);
        float inv = 1.f / tot;
        #pragma unroll
        for (int j = 0; j < 3; j++) {
            int s = tid + j * 256;
            if (s < S_SP) L[s] = e[j] * inv;
        }
    }
}

__global__ void k_major(const float* __restrict__ ov, float* __restrict__ out) {
    __shared__ float law[4 * 736];
    int t = blockIdx.x, hc = blockIdx.y, tid = threadIdx.x;
    for (int idx = tid; idx < 4 * 736; idx += 128) {
        int q = idx / 736, s = idx - q * 736;
        law[idx] = (s < S_SP) ? g_law[((size_t)t * 4 + q) * 736 + s] : 0.f;
    }
    __syncthreads();
    int h = hc * 128 + tid;
    float a0 = 0.f, a1 = 0.f, a2 = 0.f, a3 = 0.f;
    const float* base = ov + ((size_t)t * S_SP) * H_DIM + h;
    for (int s = 0; s < S_SP; s++) {
        float v = base[(size_t)s * H_DIM];
        a0 += v * law[s];
        a1 += v * law[736 + s];
        a2 += v * law[1472 + s];
        a3 += v * law[2208 + s];
    }
    out[OUT_MAJOR + ((size_t)t * 4 + 0) * H_DIM + h] = a0;
    out[OUT_MAJOR + ((size_t)t * 4 + 1) * H_DIM + h] = a1;
    out[OUT_MAJOR + ((size_t)t * 4 + 2) * H_DIM + h] = a2;
    out[OUT_MAJOR + ((size_t)t * 4 + 3) * H_DIM + h] = a3;
}

__global__ void k_finpred(const float* __restrict__ w1, const float* __restrict__ b1,
                          const float* __restrict__ w2, const float* __restrict__ b2,
                          float* __restrict__ out) {
    int b = blockIdx.x, tid = threadIdx.x;
    __shared__ float gsh[32];
    __shared__ float gsum_sh;
    __shared__ float fr[H_DIM];
    __shared__ float hid[E_DIM];
    __shared__ float lg[NE];
    if (tid < 32) {
        int p = tid >> 2, q = tid & 3;
        gsh[tid] = g_gsig[(b * P_PAT + p) * 4 + q];
    }
    __syncthreads();
    if (tid == 0) {
        float s = 0.f;
        for (int i = 0; i < 32; i++) s += gsh[i];
        gsum_sh = s;
    }
    __syncthreads();
    float denom = gsum_sh / 32.f + 1e-8f;
    int nh = (tid < 128) ? 5 : 4;
    for (int j = 0; j < nh; j++) {
        int h = tid + j * 256;
        float acc = 0.f;
        for (int idx = 0; idx < 32; idx++) {
            int p = idx >> 2, q = idx & 3;
            acc += out[OUT_MAJOR + ((size_t)(b * P_PAT + p) * 4 + q) * H_DIM + h] * gsh[idx];
        }
        float fin = (acc / 32.f) / denom;
        fr[h] = fin;
        out[OUT_FINAL + (size_t)b * H_DIM + h] = fin;
    }
    __syncthreads();
    int wid = tid >> 5, lane = tid & 31;
    for (int o = wid; o < E_DIM; o += 8) {
        float acc = 0.f;
        const float* wr = w1 + (size_t)o * H_DIM;
        for (int k = lane; k < H_DIM; k += 32) acc += wr[k] * fr[k];
        #pragma unroll
        for (int off = 16; off; off >>= 1) acc += __shfl_xor_sync(0xffffffffu, acc, off);
        if (lane == 0) hid[o] = gelu_exact(acc + b1[o]);
    }
    __syncthreads();
    for (int n = 0; n < NE; n++) {
        float v = hid[tid] * w2[n * E_DIM + tid] + hid[tid + 256] * w2[n * E_DIM + tid + 256];
        float tot = blockSum256(v);
        if (tid == 0) lg[n] = tot + b2[n];
    }
    __syncthreads();
    if (tid == 0) {
        float mx = -INFINITY;
        for (int n = 0; n < NE; n++) mx = fmaxf(mx, lg[n]);
        float sum = 0.f;
        float e[NE];
        for (int n = 0; n < NE; n++) { e[n] = expf(lg[n] - mx); sum += e[n]; }
        for (int n = 0; n < NE; n++) out[OUT_PREDS + b * NE + n] = e[n] / sum;
    }
}

extern "C" void kernel_launch(void* const* d_in, const int* in_sizes, int n_in,
                              void* d_out, int out_size) {
    const float* ov      = (const float*)d_in[0];
    const float* sig     = (const float*)d_in[1];
    const float* emo     = (const float*)d_in[2];
    const float* pool_w  = (const float*)d_in[3];
    const float* pool_b  = (const float*)d_in[4];
    const float* cls_w1  = (const float*)d_in[5];
    const float* cls_b1  = (const float*)d_in[6];
    const float* cls_w2  = (const float*)d_in[7];
    const float* cls_b2  = (const float*)d_in[8];
    const float* sig_w   = (const float*)d_in[9];
    const float* sig_b   = (const float*)d_in[10];
    const float* prm_w   = (const float*)d_in[11];
    const float* prm_b   = (const float*)d_in[12];
    const float* pred_w1 = (const float*)d_in[13];
    const float* pred_b1 = (const float*)d_in[14];
    const float* pred_w2 = (const float*)d_in[15];
    const float* pred_b2 = (const float*)d_in[16];
    const float* q_w     = (const float*)d_in[17];
    const float* q_b     = (const float*)d_in[18];
    const float* k_w     = (const float*)d_in[19];
    const float* k_b     = (const float*)d_in[20];
    float* out = (float*)d_out;

    cudaFuncSetAttribute(k_sig_mma, cudaFuncAttributeMaxDynamicSharedMemorySize, SM2_TOTAL);

    k_wsplit<<<1024, 256>>>(sig_w);
    k_pool<<<dim3(B_IMG, 9), 128>>>(ov, pool_w);
    k_cls1<<<64, 256>>>(cls_w1, cls_b1, pool_b);
    k_cls2<<<64, 256>>>(cls_w2, cls_b2);
    k_puv<<<dim3(16, NL), 256>>>(emo, prm_w);
    k_prompts2<<<dim3(NE, B_IMG, NL), 256>>>(prm_b);
    k_sig_mma<<<dim3(12, T_TOK, NL * 2), 256, SM2_TOTAL>>>(sig, sig_b);
    k_softmax_mean<<<T_TOK * NE, 256>>>();
    k_matt<<<T_TOK, 256>>>();
    k_tok<<<dim3(T_TOK, 9), 128>>>(ov);
    k_qproj<<<T_TOK, 256>>>(q_w, q_b);
    k_kq<<<dim3(T_TOK, 9), 256>>>(k_w, k_b);
    k_logits<<<dim3(T_TOK, 6), 128>>>(ov);
    k_soft4<<<T_TOK, 256>>>();
    k_major<<<dim3(T_TOK, 9), 128>>>(ov, out);
    k_finpred<<<B_IMG, 256>>>(pred_w1, pred_b1, pred_w2, pred_b2, out);
}

// round 15
// speedup vs baseline: 2.1305x; 1.4533x over previous
#include <cuda_runtime.h>
#include <cuda_fp16.h>
#include <math.h>
#include <stdint.h>

#define T_TOK 64
#define S_SP  729
#define H_DIM 1152
#define E_DIM 512
#define NE    9
#define NL    4
#define B_IMG 8
#define P_PAT 8

#define OUT_MAJOR 0
#define OUT_FINAL (T_TOK * 4 * H_DIM)
#define OUT_PREDS (OUT_FINAL + B_IMG * H_DIM)

__device__ float g_poolpart[B_IMG * 9 * H_DIM];
__device__ float g_hidden [B_IMG * E_DIM];
__device__ float g_cls    [B_IMG * E_DIM];
__device__ float g_puv    [NL * 17 * E_DIM];
__device__ float g_prompts[NL * B_IMG * NE * E_DIM];
__device__ float g_part   [(size_t)NL * T_TOK * 2 * 10 * S_SP];
__device__ float g_meanatt[T_TOK * NE * S_SP];
__device__ float g_pes    [T_TOK * NE];
__device__ float g_gsig   [T_TOK * 4];
__device__ float g_wq     [T_TOK * 4 * 736];
__device__ float g_sp     [T_TOK * 4];
__device__ float g_tokens [T_TOK * 4 * H_DIM];
__device__ float g_Q      [T_TOK * 4 * E_DIM];
__device__ float g_KQ     [T_TOK * 4 * H_DIM];
__device__ float g_qkb    [T_TOK * 4];
__device__ float g_law    [T_TOK * 4 * 736];
__device__ __align__(16) __half g_Whi[(size_t)NL * E_DIM * H_DIM];

#define WSCALE 32.0f

__device__ __forceinline__ uint32_t smem_u32(const void* p) {
    uint32_t a;
    asm("{ .reg .u64 t; cvta.to.shared.u64 t, %1; cvt.u32.u64 %0, t; }" : "=r"(a) : "l"(p));
    return a;
}
__device__ __forceinline__ void cpasync16(uint32_t dst, const void* src) {
    asm volatile("cp.async.cg.shared.global [%0], [%1], 16;" :: "r"(dst), "l"(src));
}
#define CP_COMMIT() asm volatile("cp.async.commit_group;" ::: "memory")
#define CP_WAIT1()  asm volatile("cp.async.wait_group 1;" ::: "memory")

__device__ __forceinline__ float blockSum256(float v) {
    __shared__ float red[8];
    int lane = threadIdx.x & 31, wid = threadIdx.x >> 5;
    #pragma unroll
    for (int o = 16; o; o >>= 1) v += __shfl_xor_sync(0xffffffffu, v, o);
    if (lane == 0) red[wid] = v;
    __syncthreads();
    if (wid == 0) {
        float r = (lane < 8) ? red[lane] : 0.f;
        #pragma unroll
        for (int o = 4; o; o >>= 1) r += __shfl_xor_sync(0xffffffffu, r, o);
        if (lane == 0) red[0] = r;
    }
    __syncthreads();
    float r = red[0];
    __syncthreads();
    return r;
}
__device__ __forceinline__ float blockMax256(float v) {
    __shared__ float red[8];
    int lane = threadIdx.x & 31, wid = threadIdx.x >> 5;
    #pragma unroll
    for (int o = 16; o; o >>= 1) v = fmaxf(v, __shfl_xor_sync(0xffffffffu, v, o));
    if (lane == 0) red[wid] = v;
    __syncthreads();
    if (wid == 0) {
        float r = (lane < 8) ? red[lane] : -INFINITY;
        #pragma unroll
        for (int o = 4; o; o >>= 1) r = fmaxf(r, __shfl_xor_sync(0xffffffffu, r, o));
        if (lane == 0) red[0] = r;
    }
    __syncthreads();
    float r = red[0];
    __syncthreads();
    return r;
}
__device__ __forceinline__ float gelu_exact(float x) {
    return 0.5f * x * (1.0f + erff(x * 0.7071067811865475f));
}
__device__ __forceinline__ uint32_t pk2h(__half a, __half b) {
    return ((uint32_t)__half_as_ushort(b) << 16) | (uint32_t)__half_as_ushort(a);
}
__device__ __forceinline__ void mmaf16(float* d, const uint32_t* a, uint32_t b0, uint32_t b1) {
    asm volatile(
        "mma.sync.aligned.m16n8k16.row.col.f32.f16.f16.f32 "
        "{%0,%1,%2,%3}, {%4,%5,%6,%7}, {%8,%9}, {%0,%1,%2,%3};"
        : "+f"(d[0]), "+f"(d[1]), "+f"(d[2]), "+f"(d[3])
        : "r"(a[0]), "r"(a[1]), "r"(a[2]), "r"(a[3]), "r"(b0), "r"(b1));
}

__global__ void k_wsplit(const float* __restrict__ sw) {
    const size_t N = (size_t)NL * E_DIM * H_DIM;
    for (size_t i = (size_t)blockIdx.x * 256 + threadIdx.x; i < N; i += (size_t)gridDim.x * 256)
        g_Whi[i] = __float2half(sw[i] * WSCALE);
}

__global__ void k_pool(const float* __restrict__ ov, const float* __restrict__ pw) {
    int b = blockIdx.x, sc = blockIdx.y, tid = threadIdx.x;
    float acc[9];
    #pragma unroll
    for (int j = 0; j < 9; j++) acc[j] = 0.f;
    const float* base = ov + (size_t)(b * P_PAT) * S_SP * H_DIM + (size_t)sc * 81 * H_DIM + tid;
    for (int s = 0; s < 81; s++) {
        float w = pw[sc * 81 + s];
        const float* p = base + (size_t)s * H_DIM;
        #pragma unroll
        for (int j = 0; j < 9; j++) acc[j] += w * p[j * 128];
    }
    #pragma unroll
    for (int j = 0; j < 9; j++)
        g_poolpart[((size_t)b * 9 + sc) * H_DIM + tid + j * 128] = acc[j];
}

__global__ void k_cls1(const float* __restrict__ w1, const float* __restrict__ b1,
                       const float* __restrict__ pb) {
    __shared__ float pr[B_IMG * H_DIM];
    int tid = threadIdx.x, wid = tid >> 5, lane = tid & 31;
    float pbias = pb[0];
    for (int idx = tid; idx < B_IMG * H_DIM; idx += 256) {
        int b = idx / H_DIM, h = idx - b * H_DIM;
        float s = pbias;
        #pragma unroll
        for (int sc = 0; sc < 9; sc++) s += g_poolpart[((size_t)b * 9 + sc) * H_DIM + h];
        pr[idx] = s;
    }
    __syncthreads();
    int o = blockIdx.x * 8 + wid;
    float acc[8];
    #pragma unroll
    for (int b = 0; b < 8; b++) acc[b] = 0.f;
    const float* wr = w1 + (size_t)o * H_DIM;
    for (int k = lane; k < H_DIM; k += 32) {
        float w = wr[k];
        #pragma unroll
        for (int b = 0; b < 8; b++) acc[b] += w * pr[b * H_DIM + k];
    }
    #pragma unroll
    for (int b = 0; b < 8; b++)
        #pragma unroll
        for (int off = 16; off; off >>= 1) acc[b] += __shfl_xor_sync(0xffffffffu, acc[b], off);
    if (lane == 0) {
        float bv = b1[o];
        #pragma unroll
        for (int b = 0; b < 8; b++) g_hidden[b * E_DIM + o] = gelu_exact(acc[b] + bv);
    }
}

__global__ void k_cls2(const float* __restrict__ w2, const float* __restrict__ b2) {
    __shared__ float hr[B_IMG * E_DIM];
    int tid = threadIdx.x, wid = tid >> 5, lane = tid & 31;
    for (int idx = tid; idx < B_IMG * E_DIM; idx += 256) hr[idx] = g_hidden[idx];
    __syncthreads();
    int o = blockIdx.x * 8 + wid;
    float acc[8];
    #pragma unroll
    for (int b = 0; b < 8; b++) acc[b] = 0.f;
    const float* wr = w2 + (size_t)o * E_DIM;
    for (int k = lane; k < E_DIM; k += 32) {
        float w = wr[k];
        #pragma unroll
        for (int b = 0; b < 8; b++) acc[b] += w * hr[b * E_DIM + k];
    }
    #pragma unroll
    for (int b = 0; b < 8; b++)
        #pragma unroll
        for (int off = 16; off; off >>= 1) acc[b] += __shfl_xor_sync(0xffffffffu, acc[b], off);
    if (lane == 0) {
        float bv = b2[o];
        #pragma unroll
        for (int b = 0; b < 8; b++) g_cls[b * E_DIM + o] = acc[b] + bv;
    }
}

__global__ void k_puv(const float* __restrict__ emo, const float* __restrict__ pw) {
    int oc = blockIdx.x, i = blockIdx.y;
    int tid = threadIdx.x, wid = tid >> 5, lane = tid & 31;
    __shared__ float es[NE * E_DIM];
    __shared__ float cs[B_IMG * E_DIM];
    for (int idx = tid; idx < NE * E_DIM; idx += 256) es[idx] = emo[idx];
    for (int idx = tid; idx < B_IMG * E_DIM; idx += 256) cs[idx] = g_cls[idx];
    __syncthreads();
    for (int oi = wid; oi < 32; oi += 8) {
        int o = oc * 32 + oi;
        const float* wr = pw + ((size_t)i * E_DIM + o) * 1024;
        float acc[17];
        #pragma unroll
        for (int j = 0; j < 17; j++) acc[j] = 0.f;
        for (int c = lane; c < 512; c += 32) {
            float w1 = wr[c];
            #pragma unroll
            for (int n = 0; n < NE; n++) acc[n] += w1 * es[n * 512 + c];
            float w2 = wr[512 + c];
            #pragma unroll
            for (int b = 0; b < B_IMG; b++) acc[9 + b] += w2 * cs[b * 512 + c];
        }
        #pragma unroll
        for (int j = 0; j < 17; j++)
            #pragma unroll
            for (int off = 16; off; off >>= 1) acc[j] += __shfl_xor_sync(0xffffffffu, acc[j], off);
        if (lane == 0) {
            #pragma unroll
            for (int j = 0; j < 17; j++) g_puv[((size_t)i * 17 + j) * 512 + o] = acc[j];
        }
    }
}

__global__ void k_prompts2(const float* __restrict__ pb) {
    int n = blockIdx.x, b = blockIdx.y, i = blockIdx.z;
    int tid = threadIdx.x;
    int o1 = tid, o2 = tid + 256;
    float r1 = g_puv[((size_t)i * 17 + n) * 512 + o1] + g_puv[((size_t)i * 17 + 9 + b) * 512 + o1]
             + pb[i * 512 + o1];
    float r2 = g_puv[((size_t)i * 17 + n) * 512 + o2] + g_puv[((size_t)i * 17 + 9 + b) * 512 + o2]
             + pb[i * 512 + o2];
    float nrm = blockSum256(r1 * r1 + r2 * r2);
    float inv = rsqrtf(nrm);
    size_t base = ((size_t)(i * B_IMG + b) * NE + n) * E_DIM;
    g_prompts[base + o1] = r1 * inv;
    g_prompts[base + o2] = r2 * inv;
}

// ======= sig GEMM: fp16 SINGLE product (scaled W), grid (12,64,8), 2 CTA/SM =======
#define NCH 36
#define SM2_PSM   0          // 9216
#define SM2_SBI   9216       // 1024
#define SM2_RED   10240      // 2560
#define SM2_A     12800      // 2 bufs x 5120 = 10240
#define SM2_W     23040      // 2 bufs x 20480 = 40960 (hi plane only) -> ends 64000
#define SM2_YSM   12800      // union: 64*260*4 = 66560 -> ends 79360
#define SM2_TOTAL 79360
#define Y_STR 260

__global__ void __launch_bounds__(256, 2)
k_sig_mma(const float* __restrict__ sig, const float* __restrict__ sb) {
    extern __shared__ char smem[];
    uint32_t sbase = smem_u32(smem);
    float* Psm = reinterpret_cast<float*>(smem + SM2_PSM);
    float* Sbi = reinterpret_cast<float*>(smem + SM2_SBI);
    float* red = reinterpret_cast<float*>(smem + SM2_RED);
    float* ysm = reinterpret_cast<float*>(smem + SM2_YSM);

    int tid = threadIdx.x, wid = tid >> 5, lane = tid & 31;
    int wm = wid >> 2, wn = wid & 3;
    int g = lane >> 2, tig = lane & 3;
    int s0 = blockIdx.x * 64;
    int t = blockIdx.y;
    int i = blockIdx.z >> 1, half = blockIdx.z & 1;
    int b = t >> 3;

    {
        size_t pbase = ((size_t)(i * B_IMG + b) * NE) * E_DIM + half * 256;
        for (int idx = tid; idx < NE * 256; idx += 256) {
            int n = idx >> 8, cc = idx & 255;
            Psm[idx] = g_prompts[pbase + (size_t)n * E_DIM + cc];
        }
        for (int idx = tid; idx < 256; idx += 256)
            Sbi[idx] = WSCALE * sb[i * E_DIM + half * 256 + idx];
        for (int idx = tid; idx < 640; idx += 256) red[idx] = 0.f;
    }

    const float* Xbase = sig + ((size_t)(i * T_TOK + t) * S_SP) * H_DIM;
    const char* WH = reinterpret_cast<const char*>(g_Whi)
                   + ((size_t)i * E_DIM + half * 256) * H_DIM * 2;

    float acc[2][8][4];
    #pragma unroll
    for (int mt = 0; mt < 2; mt++)
        #pragma unroll
        for (int nt = 0; nt < 8; nt++)
            #pragma unroll
            for (int c = 0; c < 4; c++) acc[mt][nt][c] = 0.f;

    int xrow = tid >> 2, xkc = tid & 3;
    int xs = s0 + xrow;
    const float* xptr = (xs < S_SP) ? (Xbase + (size_t)xs * H_DIM + xkc * 8) : nullptr;
    float xv[8];

#define ISSUE_W(CH, BUF) do { \
    const char* sH = WH + ((size_t)tid * H_DIM + (CH) * 32) * 2; \
    uint32_t dH = sbase + SM2_W + (BUF) * 20480 + tid * 80; \
    cpasync16(dH, sH); cpasync16(dH + 16, sH + 16); \
    cpasync16(dH + 32, sH + 32); cpasync16(dH + 48, sH + 48); \
} while (0)

#define LOAD_X(CH) do { \
    if (xptr) { \
        const float* p_ = xptr + (CH) * 32; \
        float4 f0_ = *reinterpret_cast<const float4*>(p_); \
        float4 f1_ = *reinterpret_cast<const float4*>(p_ + 4); \
        xv[0]=f0_.x; xv[1]=f0_.y; xv[2]=f0_.z; xv[3]=f0_.w; \
        xv[4]=f1_.x; xv[5]=f1_.y; xv[6]=f1_.z; xv[7]=f1_.w; \
    } else { \
        _Pragma("unroll") for (int j_ = 0; j_ < 8; j_++) xv[j_] = 0.f; \
    } \
} while (0)

#define STORE_A(BUF) do { \
    uint32_t hq_[4]; \
    _Pragma("unroll") \
    for (int j_ = 0; j_ < 4; j_++) \
        hq_[j_] = pk2h(__float2half(xv[2*j_]), __float2half(xv[2*j_+1])); \
    char* aH = smem + SM2_A + (BUF) * 5120 + xrow * 80 + xkc * 16; \
    *reinterpret_cast<uint4*>(aH) = make_uint4(hq_[0], hq_[1], hq_[2], hq_[3]); \
} while (0)

    ISSUE_W(0, 0); CP_COMMIT();
    LOAD_X(0);
    ISSUE_W(1, 1); CP_COMMIT();
    STORE_A(0);
    LOAD_X(1);

    for (int ch = 0; ch < NCH; ch++) {
        int buf = ch & 1;
        if (ch > 0) {
            STORE_A(buf);
            if (ch + 1 < NCH) LOAD_X(ch + 1);
        }
        CP_WAIT1();
        __syncthreads();

        const uint32_t* AH  = reinterpret_cast<const uint32_t*>(smem + SM2_A + buf * 5120);
        const uint32_t* WHs = reinterpret_cast<const uint32_t*>(smem + SM2_W + buf * 20480);

        #pragma unroll
        for (int h = 0; h < 2; h++) {
            uint32_t ah[2][4];
            #pragma unroll
            for (int mt = 0; mt < 2; mt++) {
                int base = (wm * 32 + mt * 16 + g) * 20 + h * 8 + tig;
                ah[mt][0] = AH[base];     ah[mt][1] = AH[base + 160];
                ah[mt][2] = AH[base + 4]; ah[mt][3] = AH[base + 164];
            }
            #pragma unroll
            for (int nt = 0; nt < 8; nt++) {
                int wb = (wn * 64 + nt * 8 + g) * 20 + h * 8 + tig;
                uint32_t b0h = WHs[wb], b1h = WHs[wb + 4];
                mmaf16(acc[0][nt], ah[0], b0h, b1h);
                mmaf16(acc[1][nt], ah[1], b0h, b1h);
            }
        }
        __syncthreads();
        if (ch + 2 < NCH) ISSUE_W(ch + 2, buf);
        CP_COMMIT();
    }

    // epilogue (scale-invariant): bias(x32) + partial L2-norm + partial prompt dots
    #pragma unroll
    for (int mt = 0; mt < 2; mt++) {
        int row = wm * 32 + mt * 16 + g;
        #pragma unroll
        for (int nt = 0; nt < 8; nt++) {
            int col = wn * 64 + nt * 8 + tig * 2;
            float b0 = Sbi[col], b1 = Sbi[col + 1];
            *reinterpret_cast<float2*>(&ysm[row * Y_STR + col]) =
                make_float2(acc[mt][nt][0] + b0, acc[mt][nt][1] + b1);
            *reinterpret_cast<float2*>(&ysm[(row + 8) * Y_STR + col]) =
                make_float2(acc[mt][nt][2] + b0, acc[mt][nt][3] + b1);
        }
    }
    __syncthreads();
    for (int r8 = 0; r8 < 8; r8++) {
        int row = wid * 8 + r8;
        float v[10];
        #pragma unroll
        for (int j = 0; j < 10; j++) v[j] = 0.f;
        for (int cc = lane; cc < 256; cc += 32) {
            float y = ysm[row * Y_STR + cc];
            v[0] += y * y;
            #pragma unroll
            for (int n = 0; n < NE; n++) v[1 + n] += y * Psm[n * 256 + cc];
        }
        #pragma unroll
        for (int j = 0; j < 10; j++)
            #pragma unroll
            for (int off = 16; off; off >>= 1) v[j] += __shfl_xor_sync(0xffffffffu, v[j], off);
        if (lane == 0) {
            #pragma unroll
            for (int j = 0; j < 10; j++) red[row * 10 + j] = v[j];
        }
    }
    __syncthreads();

    if (tid < 64) {
        int s = s0 + tid;
        if (s < S_SP) {
            size_t base = ((((size_t)i * T_TOK + t) * 2 + half) * 10) * S_SP + s;
            #pragma unroll
            for (int j = 0; j < 10; j++)
                g_part[base + (size_t)j * S_SP] = red[tid * 10 + j];
        }
    }
#undef ISSUE_W
#undef LOAD_X
#undef STORE_A
}

__global__ void k_softmax_mean() {
    int tn = blockIdx.x;
    int t = tn / NE, n = tn % NE;
    int tid = threadIdx.x;
    float accm[3] = {0.f, 0.f, 0.f};
    for (int i = 0; i < NL; i++) {
        const float* p0 = g_part + ((((size_t)i * T_TOK + t) * 2 + 0) * 10) * S_SP;
        const float* p1 = g_part + ((((size_t)i * T_TOK + t) * 2 + 1) * 10) * S_SP;
        float x[3];
        float mx = -INFINITY;
        #pragma unroll
        for (int j = 0; j < 3; j++) {
            int s = tid + j * 256;
            if (s < S_SP) {
                float nsq = p0[s] + p1[s];
                float d = p0[(size_t)(1 + n) * S_SP + s] + p1[(size_t)(1 + n) * S_SP + s];
                x[j] = 100.f * d * rsqrtf(nsq);
            } else x[j] = -INFINITY;
            mx = fmaxf(mx, x[j]);
        }
        mx = blockMax256(mx);
        float lsum = 0.f;
        float e[3];
        #pragma unroll
        for (int j = 0; j < 3; j++) {
            int s = tid + j * 256;
            e[j] = (s < S_SP) ? expf(x[j] - mx) : 0.f;
            lsum += e[j];
        }
        float tot = blockSum256(lsum);
        float inv = 0.25f / tot;
        #pragma unroll
        for (int j = 0; j < 3; j++) accm[j] += e[j] * inv;
    }
    float psum = 0.f;
    size_t obase = ((size_t)t * NE + n) * S_SP;
    #pragma unroll
    for (int j = 0; j < 3; j++) {
        int s = tid + j * 256;
        if (s < S_SP) {
            g_meanatt[obase + s] = accm[j];
            psum += accm[j];
        }
    }
    float tot = blockSum256(psum);
    if (tid == 0) g_pes[t * NE + n] = tot / (float)S_SP;
}

__global__ void k_matt() {
    int t = blockIdx.x, tid = threadIdx.x;
    float bsum[4] = {0.f, 0.f, 0.f, 0.f};
    #pragma unroll
    for (int j = 0; j < 3; j++) {
        int s = tid + j * 256;
        if (s < S_SP) {
            float m = -INFINITY;
            #pragma unroll
            for (int n = 0; n < NE; n++)
                m = fmaxf(m, g_meanatt[((size_t)t * NE + n) * S_SP + s]);
            int r = s / 27, c = s - r * 27;
            float w0 = (r < 14 && c < 14) ? m : 0.f;
            float w1 = (r < 14 && c >= 13) ? m : 0.f;
            float w2 = (r >= 13 && c < 14) ? m : 0.f;
            float w3 = (r >= 13 && c >= 13) ? m : 0.f;
            size_t wb = (size_t)t * 4 * 736 + s;
            g_wq[wb] = w0;
            g_wq[wb + 736] = w1;
            g_wq[wb + 1472] = w2;
            g_wq[wb + 2208] = w3;
            bsum[0] += w0; bsum[1] += w1; bsum[2] += w2; bsum[3] += w3;
        }
    }
    #pragma unroll
    for (int q = 0; q < 4; q++) {
        float tot = blockSum256(bsum[q]);
        if (tid == 0) g_sp[t * 4 + q] = tot / 196.f;
    }
    if (tid == 0) {
        float pm = -INFINITY;
        for (int n = 0; n < NE; n++) pm = fmaxf(pm, g_pes[t * NE + n]);
        g_gsig[t * 4 + 0] = g_sp[t * 4 + 0] * pm;
        g_gsig[t * 4 + 1] = g_sp[t * 4 + 1] * pm;
        g_gsig[t * 4 + 2] = g_sp[t * 4 + 2] * pm;
        g_gsig[t * 4 + 3] = g_sp[t * 4 + 3] * pm;
    }
}

__global__ void k_tok(const float* __restrict__ ov) {
    __shared__ float wqs[4 * 736];
    __shared__ float sps[4];
    int t = blockIdx.x, hc = blockIdx.y, tid = threadIdx.x;
    for (int idx = tid; idx < 4 * 736; idx += 128) wqs[idx] = g_wq[(size_t)t * 4 * 736 + idx];
    if (tid < 4) sps[tid] = g_sp[t * 4 + tid];
    __syncthreads();
    int h = hc * 128 + tid;
    float a0 = 0.f, a1 = 0.f, a2 = 0.f, a3 = 0.f;
    const float* base = ov + ((size_t)t * S_SP) * H_DIM + h;
    for (int s = 0; s < S_SP; s++) {
        float v = base[(size_t)s * H_DIM];
        a0 += v * wqs[s];
        a1 += v * wqs[736 + s];
        a2 += v * wqs[1472 + s];
        a3 += v * wqs[2208 + s];
    }
    g_tokens[((size_t)t * 4 + 0) * H_DIM + h] = (a0 * (1.f / 196.f)) / (sps[0] + 1e-8f);
    g_tokens[((size_t)t * 4 + 1) * H_DIM + h] = (a1 * (1.f / 196.f)) / (sps[1] + 1e-8f);
    g_tokens[((size_t)t * 4 + 2) * H_DIM + h] = (a2 * (1.f / 196.f)) / (sps[2] + 1e-8f);
    g_tokens[((size_t)t * 4 + 3) * H_DIM + h] = (a3 * (1.f / 196.f)) / (sps[3] + 1e-8f);
}

__global__ void k_qproj(const float* __restrict__ qw, const float* __restrict__ qb) {
    int t = blockIdx.x, tid = threadIdx.x;
    __shared__ float toks[4 * H_DIM];
    for (int idx = tid; idx < 4 * H_DIM; idx += 256) toks[idx] = g_tokens[(size_t)t * 4 * H_DIM + idx];
    __syncthreads();
    int wid = tid >> 5, lane = tid & 31;
    for (int o = wid; o < E_DIM; o += 8) {
        float acc[4] = {0.f, 0.f, 0.f, 0.f};
        const float* wr = qw + (size_t)o * H_DIM;
        for (int k = lane; k < H_DIM; k += 32) {
            float w = wr[k];
            #pragma unroll
            for (int q = 0; q < 4; q++) acc[q] += w * toks[q * H_DIM + k];
        }
        #pragma unroll
        for (int off = 16; off; off >>= 1)
            #pragma unroll
            for (int q = 0; q < 4; q++) acc[q] += __shfl_xor_sync(0xffffffffu, acc[q], off);
        if (lane == 0) {
            float bv = qb[o];
            #pragma unroll
            for (int q = 0; q < 4; q++) g_Q[((size_t)t * 4 + q) * E_DIM + o] = acc[q] + bv;
        }
    }
}

__global__ void k_kq(const float* __restrict__ kw, const float* __restrict__ kb) {
    int t = blockIdx.x, hc = blockIdx.y;
    int tid = threadIdx.x;
    __shared__ float Qs[4 * E_DIM];
    for (int idx = tid; idx < 4 * E_DIM; idx += 256) Qs[idx] = g_Q[(size_t)t * 4 * E_DIM + idx];
    __syncthreads();
    int h = hc * 128 + (tid >> 1);
    int q0 = (tid & 1) * 2;
    float a0 = 0.f, a1 = 0.f;
    const float* kcol = kw + h;
    for (int e = 0; e < E_DIM; e++) {
        float kv = kcol[(size_t)e * H_DIM];
        a0 += kv * Qs[(q0 + 0) * E_DIM + e];
        a1 += kv * Qs[(q0 + 1) * E_DIM + e];
    }
    g_KQ[((size_t)t * 4 + q0 + 0) * H_DIM + h] = a0;
    g_KQ[((size_t)t * 4 + q0 + 1) * H_DIM + h] = a1;

    if (hc == 0 && tid < 128) {
        int wid = tid >> 5, lane = tid & 31;
        float acc = 0.f;
        for (int e = lane; e < E_DIM; e += 32) acc += Qs[wid * E_DIM + e] * kb[e];
        #pragma unroll
        for (int off = 16; off; off >>= 1) acc += __shfl_xor_sync(0xffffffffu, acc, off);
        if (lane == 0) g_qkb[t * 4 + wid] = acc;
    }
}

__global__ void k_logits(const float* __restrict__ ov) {
    __shared__ float KQs[4 * H_DIM];
    __shared__ float qkbs[4];
    int t = blockIdx.x, sc = blockIdx.y, tid = threadIdx.x;
    int wid = tid >> 5, lane = tid & 31;
    for (int idx = tid; idx < 4 * H_DIM; idx += 128) KQs[idx] = g_KQ[(size_t)t * 4 * H_DIM + idx];
    if (tid < 4) qkbs[tid] = g_qkb[t * 4 + tid];
    __syncthreads();
    const float RS = 0.04419417382415922f;
    for (int s = sc * 128 + wid; s < min(sc * 128 + 128, S_SP); s += 4) {
        float acc[4] = {0.f, 0.f, 0.f, 0.f};
        const float* orow = ov + ((size_t)t * S_SP + s) * H_DIM;
        for (int h = lane; h < H_DIM; h += 32) {
            float vv = orow[h];
            #pragma unroll
            for (int q = 0; q < 4; q++) acc[q] += vv * KQs[q * H_DIM + h];
        }
        #pragma unroll
        for (int off = 16; off; off >>= 1)
            #pragma unroll
            for (int q = 0; q < 4; q++) acc[q] += __shfl_xor_sync(0xffffffffu, acc[q], off);
        if (lane == 0) {
            #pragma unroll
            for (int q = 0; q < 4; q++)
                g_law[((size_t)t * 4 + q) * 736 + s] = (acc[q] + qkbs[q]) * RS;
        }
    }
}

__global__ void k_soft4() {
    int t = blockIdx.x, tid = threadIdx.x;
    for (int q = 0; q < 4; q++) {
        float* L = g_law + ((size_t)t * 4 + q) * 736;
        float x[3];
        float mx = -INFINITY;
        #pragma unroll
        for (int j = 0; j < 3; j++) {
            int s = tid + j * 256;
            x[j] = (s < S_SP) ? L[s] : -INFINITY;
            mx = fmaxf(mx, x[j]);
        }
        mx = blockMax256(mx);
        float lsum = 0.f;
        float e[3];
        #pragma unroll
        for (int j = 0; j < 3; j++) {
            int s = tid + j * 256;
            e[j] = (s < S_SP) ? expf(x[j] - mx) : 0.f;
            lsum += e[j];
        }
        float tot = blockSum256(lsum);
        float inv = 1.f / tot;
        #pragma unroll
        for (int j = 0; j < 3; j++) {
            int s = tid + j * 256;
            if (s < S_SP) L[s] = e[j] * inv;
        }
    }
}

__global__ void k_major(const float* __restrict__ ov, float* __restrict__ out) {
    __shared__ float law[4 * 736];
    int t = blockIdx.x, hc = blockIdx.y, tid = threadIdx.x;
    for (int idx = tid; idx < 4 * 736; idx += 128) {
        int q = idx / 736, s = idx - q * 736;
        law[idx] = (s < S_SP) ? g_law[((size_t)t * 4 + q) * 736 + s] : 0.f;
    }
    __syncthreads();
    int h = hc * 128 + tid;
    float a0 = 0.f, a1 = 0.f, a2 = 0.f, a3 = 0.f;
    const float* base = ov + ((size_t)t * S_SP) * H_DIM + h;
    for (int s = 0; s < S_SP; s++) {
        float v = base[(size_t)s * H_DIM];
        a0 += v * law[s];
        a1 += v * law[736 + s];
        a2 += v * law[1472 + s];
        a3 += v * law[2208 + s];
    }
    out[OUT_MAJOR + ((size_t)t * 4 + 0) * H_DIM + h] = a0;
    out[OUT_MAJOR + ((size_t)t * 4 + 1) * H_DIM + h] = a1;
    out[OUT_MAJOR + ((size_t)t * 4 + 2) * H_DIM + h] = a2;
    out[OUT_MAJOR + ((size_t)t * 4 + 3) * H_DIM + h] = a3;
}

__global__ void k_finpred(const float* __restrict__ w1, const float* __restrict__ b1,
                          const float* __restrict__ w2, const float* __restrict__ b2,
                          float* __restrict__ out) {
    int b = blockIdx.x, tid = threadIdx.x;
    __shared__ float gsh[32];
    __shared__ float gsum_sh;
    __shared__ float fr[H_DIM];
    __shared__ float hid[E_DIM];
    __shared__ float lg[NE];
    if (tid < 32) {
        int p = tid >> 2, q = tid & 3;
        gsh[tid] = g_gsig[(b * P_PAT + p) * 4 + q];
    }
    __syncthreads();
    if (tid == 0) {
        float s = 0.f;
        for (int i = 0; i < 32; i++) s += gsh[i];
        gsum_sh = s;
    }
    __syncthreads();
    float denom = gsum_sh / 32.f + 1e-8f;
    int nh = (tid < 128) ? 5 : 4;
    for (int j = 0; j < nh; j++) {
        int h = tid + j * 256;
        float acc = 0.f;
        for (int idx = 0; idx < 32; idx++) {
            int p = idx >> 2, q = idx & 3;
            acc += out[OUT_MAJOR + ((size_t)(b * P_PAT + p) * 4 + q) * H_DIM + h] * gsh[idx];
        }
        float fin = (acc / 32.f) / denom;
        fr[h] = fin;
        out[OUT_FINAL + (size_t)b * H_DIM + h] = fin;
    }
    __syncthreads();
    int wid = tid >> 5, lane = tid & 31;
    for (int o = wid; o < E_DIM; o += 8) {
        float acc = 0.f;
        const float* wr = w1 + (size_t)o * H_DIM;
        for (int k = lane; k < H_DIM; k += 32) acc += wr[k] * fr[k];
        #pragma unroll
        for (int off = 16; off; off >>= 1) acc += __shfl_xor_sync(0xffffffffu, acc, off);
        if (lane == 0) hid[o] = gelu_exact(acc + b1[o]);
    }
    __syncthreads();
    for (int n = 0; n < NE; n++) {
        float v = hid[tid] * w2[n * E_DIM + tid] + hid[tid + 256] * w2[n * E_DIM + tid + 256];
        float tot = blockSum256(v);
        if (tid == 0) lg[n] = tot + b2[n];
    }
    __syncthreads();
    if (tid == 0) {
        float mx = -INFINITY;
        for (int n = 0; n < NE; n++) mx = fmaxf(mx, lg[n]);
        float sum = 0.f;
        float e[NE];
        for (int n = 0; n < NE; n++) { e[n] = expf(lg[n] - mx); sum += e[n]; }
        for (int n = 0; n < NE; n++) out[OUT_PREDS + b * NE + n] = e[n] / sum;
    }
}

extern "C" void kernel_launch(void* const* d_in, const int* in_sizes, int n_in,
                              void* d_out, int out_size) {
    const float* ov      = (const float*)d_in[0];
    const float* sig     = (const float*)d_in[1];
    const float* emo     = (const float*)d_in[2];
    const float* pool_w  = (const float*)d_in[3];
    const float* pool_b  = (const float*)d_in[4];
    const float* cls_w1  = (const float*)d_in[5];
    const float* cls_b1  = (const float*)d_in[6];
    const float* cls_w2  = (const float*)d_in[7];
    const float* cls_b2  = (const float*)d_in[8];
    const float* sig_w   = (const float*)d_in[9];
    const float* sig_b   = (const float*)d_in[10];
    const float* prm_w   = (const float*)d_in[11];
    const float* prm_b   = (const float*)d_in[12];
    const float* pred_w1 = (const float*)d_in[13];
    const float* pred_b1 = (const float*)d_in[14];
    const float* pred_w2 = (const float*)d_in[15];
    const float* pred_b2 = (const float*)d_in[16];
    const float* q_w     = (const float*)d_in[17];
    const float* q_b     = (const float*)d_in[18];
    const float* k_w     = (const float*)d_in[19];
    const float* k_b     = (const float*)d_in[20];
    float* out = (float*)d_out;

    cudaFuncSetAttribute(k_sig_mma, cudaFuncAttributeMaxDynamicSharedMemorySize, SM2_TOTAL);

    k_wsplit<<<1024, 256>>>(sig_w);
    k_pool<<<dim3(B_IMG, 9), 128>>>(ov, pool_w);
    k_cls1<<<64, 256>>>(cls_w1, cls_b1, pool_b);
    k_cls2<<<64, 256>>>(cls_w2, cls_b2);
    k_puv<<<dim3(16, NL), 256>>>(emo, prm_w);
    k_prompts2<<<dim3(NE, B_IMG, NL), 256>>>(prm_b);
    k_sig_mma<<<dim3(12, T_TOK, NL * 2), 256, SM2_TOTAL>>>(sig, sig_b);
    k_softmax_mean<<<T_TOK * NE, 256>>>();
    k_matt<<<T_TOK, 256>>>();
    k_tok<<<dim3(T_TOK, 9), 128>>>(ov);
    k_qproj<<<T_TOK, 256>>>(q_w, q_b);
    k_kq<<<dim3(T_TOK, 9), 256>>>(k_w, k_b);
    k_logits<<<dim3(T_TOK, 6), 128>>>(ov);
    k_soft4<<<T_TOK, 256>>>();
    k_major<<<dim3(T_TOK, 9), 128>>>(ov, out);
    k_finpred<<<B_IMG, 256>>>(pred_w1, pred_b1, pred_w2, pred_b2, out);
}